// round 1
// baseline (speedup 1.0000x reference)
#include <cuda_runtime.h>
#include <stdint.h>
#include <math.h>

// ---------------- problem constants ----------------
#define NNODES 50000
#define NKEEP  320000
#define D_IN   128
#define D_OUT  256
#define D_HID  512
#define BN_EPS 1e-5f

// ---------------- device scratch (static: no runtime allocation) ----------------
__device__ float g_x1  [(size_t)NNODES * D_IN];
__device__ float g_agg [(size_t)NNODES * D_OUT];
__device__ float g_T   [(size_t)NNODES * D_HID];
__device__ float g_V   [(size_t)NNODES * D_OUT];
__device__ float g_HA  [(size_t)NNODES * D_OUT];
__device__ float g_HB  [(size_t)NNODES * D_OUT];
__device__ float g_REX1[(size_t)NNODES * D_IN];
__device__ float g_REX2[(size_t)NNODES * D_IN];
__device__ int   g_src1[NKEEP], g_dst1[NKEEP], g_src2[NKEEP], g_dst2[NKEEP];
__device__ unsigned char g_mA[NNODES], g_mB[NNODES];
__device__ float g_stats[2 * D_HID];                 // colsum | colsumsq
__device__ float g_sc1[D_HID], g_sh1[D_HID];
__device__ float g_sc2[D_HID], g_sh2[D_HID];
__device__ float g_acc[8];                           // 0:loss1 1:loss2 2:cl 3:cnt1 4:cnt2
__device__ int   g_flags[2];                         // 0: edges are int64; 1: mask is 4-byte

// ---------------- input-format detection ----------------
__global__ void detect_k(const int* __restrict__ e1w, const unsigned char* __restrict__ m1b) {
    if (threadIdx.x == 0 && blockIdx.x == 0) {
        int nz = 0;
        for (int i = 0; i < 64; ++i) nz += (e1w[2 * i + 1] != 0);
        g_flags[0] = (nz == 0) ? 1 : 0;   // all high words zero -> int64
        int nzb = 0;
        for (int i = 0; i < 256; ++i) if (i & 3) nzb += (m1b[i] != 0);
        g_flags[1] = (nzb == 0) ? 1 : 0;  // stride-4 zeros -> 4-byte mask
    }
}

__global__ void convedge_k(const int* __restrict__ raw, int* __restrict__ src, int* __restrict__ dst) {
    int e = blockIdx.x * 256 + threadIdx.x;
    if (e >= NKEEP) return;
    if (g_flags[0]) {  // int64: low word of element
        src[e] = raw[2 * e];
        dst[e] = raw[2 * (NKEEP + e)];
    } else {
        src[e] = raw[e];
        dst[e] = raw[NKEEP + e];
    }
}

__global__ void convmask_k(const void* __restrict__ raw, unsigned char* __restrict__ m, float* __restrict__ cnt) {
    int i = blockIdx.x * 256 + threadIdx.x;
    unsigned char v = 0;
    if (i < NNODES) {
        if (g_flags[1]) v = (((const unsigned int*)raw)[i] != 0u);  // int32 or f32: nonzero bits
        else            v = (((const unsigned char*)raw)[i] != 0);
        m[i] = v;
    }
    __shared__ int s[256];
    s[threadIdx.x] = v;
    __syncthreads();
    for (int o = 128; o; o >>= 1) {
        if (threadIdx.x < o) s[threadIdx.x] += s[threadIdx.x + o];
        __syncthreads();
    }
    if (threadIdx.x == 0) atomicAdd(cnt, (float)s[0]);
}

// ---------------- elementwise ----------------
__global__ void maskzero_k(const float* __restrict__ X, float* __restrict__ Y,
                           const unsigned char* __restrict__ m) {
    size_t i = (size_t)blockIdx.x * blockDim.x + threadIdx.x;
    if (i >= (size_t)NNODES * D_IN) return;
    int row = (int)(i >> 7);  // D_IN = 128
    Y[i] = m[row] ? 0.f : X[i];
}

__global__ void copy_k(const float* __restrict__ X, float* __restrict__ Y, size_t n4) {
    size_t i = (size_t)blockIdx.x * blockDim.x + threadIdx.x;
    if (i < n4) ((float4*)Y)[i] = ((const float4*)X)[i];
}

// apply BN scale/shift + relu (+ optional row mask), V -> H
__global__ void postbn_k(const float* __restrict__ V, float* __restrict__ H,
                         const float* __restrict__ sc, const float* __restrict__ sh,
                         const unsigned char* __restrict__ m, int C, int cshift) {
    size_t i = (size_t)blockIdx.x * blockDim.x + threadIdx.x;
    if (i >= (size_t)NNODES * C) return;
    int c = (int)(i & (size_t)(C - 1));
    float v = fmaxf(V[i] * sc[c] + sh[c], 0.f);
    if (m) {
        int row = (int)(i >> cshift);
        if (m[row]) v = 0.f;
    }
    H[i] = v;
}

// ---------------- edge scatter-add: AGG[dst] += X[src] (vector red) ----------------
__global__ void scatter_k(const float* __restrict__ X, float* __restrict__ AGG,
                          const int* __restrict__ src, const int* __restrict__ dst, int d4) {
    int e = blockIdx.x * blockDim.y + threadIdx.y;
    if (e >= NKEEP) return;
    int s = src[e], d = dst[e];
    int c = threadIdx.x;
    float4 v = ((const float4*)X)[(size_t)s * d4 + c];
    float* p = AGG + ((size_t)d * d4 + c) * 4;
    asm volatile("red.global.add.v4.f32 [%0], {%1,%2,%3,%4};"
                 :: "l"(p), "f"(v.x), "f"(v.y), "f"(v.z), "f"(v.w) : "memory");
}

// ---------------- column stats for BN ----------------
__global__ void colstats_k(const float* __restrict__ T, int C,
                           float* __restrict__ sum, float* __restrict__ sq) {
    int col = blockIdx.x * 32 + threadIdx.x;
    int r0 = blockIdx.y * 512;
    int r1 = min(r0 + 512, NNODES);
    float s = 0.f, q = 0.f;
    for (int r = r0 + threadIdx.y; r < r1; r += 8) {
        float v = T[(size_t)r * C + col];
        s += v; q += v * v;
    }
    __shared__ float ss[8][33], qs[8][33];
    ss[threadIdx.y][threadIdx.x] = s;
    qs[threadIdx.y][threadIdx.x] = q;
    __syncthreads();
    if (threadIdx.y == 0) {
#pragma unroll
        for (int j = 1; j < 8; ++j) { s += ss[j][threadIdx.x]; q += qs[j][threadIdx.x]; }
        atomicAdd(&sum[col], s);
        atomicAdd(&sq[col], q);
    }
}

__global__ void scaleshift_k(const float* __restrict__ sum, const float* __restrict__ sq,
                             const float* __restrict__ g, const float* __restrict__ b,
                             float* __restrict__ sc, float* __restrict__ sh, int C) {
    int c = blockIdx.x * blockDim.x + threadIdx.x;
    if (c >= C) return;
    const float invN = 1.f / (float)NNODES;
    float mu  = sum[c] * invN;
    float var = sq[c] * invN - mu * mu;
    float rs  = rsqrtf(var + BN_EPS);
    float s   = g[c] * rs;
    sc[c] = s;
    sh[c] = b[c] - mu * s;
}

// ---------------- fp32 SGEMM: C[M,Ncol] = A'[M,K] @ W[K,Ncol] ----------------
// TA: A' = relu(A*sc[k]+sh[k]) applied at A-tile load (fused BN+relu).
template <bool TA>
__global__ void __launch_bounds__(256, 2)
sgemm_k(const float* __restrict__ A, const float* __restrict__ W, float* __restrict__ C,
        int M, int K, int Ncol, const float* __restrict__ sc, const float* __restrict__ sh) {
    __shared__ float As[16][128];
    __shared__ float Ws[16][128];
    const int bx = blockIdx.x * 128;
    const int by = blockIdx.y * 128;
    const int tid = threadIdx.x;
    const int tr = (tid / 16) * 8;
    const int tc = (tid % 16) * 8;
    const int ar = tid >> 2;           // 0..63
    const int ac = (tid & 3) * 4;      // 0,4,8,12
    const int wr = tid >> 5;           // 0..7
    const int wc = (tid & 31) * 4;     // 0..124
    float acc[8][8] = {};

    for (int kb = 0; kb < K; kb += 16) {
#pragma unroll
        for (int it = 0; it < 2; ++it) {
            int row = by + ar + it * 64;
            float4 v = make_float4(0.f, 0.f, 0.f, 0.f);
            if (row < M) v = *(const float4*)(A + (size_t)row * K + kb + ac);
            if (TA) {
                int k0 = kb + ac;
                v.x = fmaxf(v.x * sc[k0 + 0] + sh[k0 + 0], 0.f);
                v.y = fmaxf(v.y * sc[k0 + 1] + sh[k0 + 1], 0.f);
                v.z = fmaxf(v.z * sc[k0 + 2] + sh[k0 + 2], 0.f);
                v.w = fmaxf(v.w * sc[k0 + 3] + sh[k0 + 3], 0.f);
            }
            As[ac + 0][ar + it * 64] = v.x;
            As[ac + 1][ar + it * 64] = v.y;
            As[ac + 2][ar + it * 64] = v.z;
            As[ac + 3][ar + it * 64] = v.w;
        }
#pragma unroll
        for (int it = 0; it < 2; ++it) {
            int krow = kb + wr + it * 8;
            *(float4*)&Ws[wr + it * 8][wc] = *(const float4*)(W + (size_t)krow * Ncol + bx + wc);
        }
        __syncthreads();
#pragma unroll
        for (int k = 0; k < 16; ++k) {
            float4 a0 = *(const float4*)&As[k][tr];
            float4 a1 = *(const float4*)&As[k][tr + 4];
            float4 b0 = *(const float4*)&Ws[k][tc];
            float4 b1 = *(const float4*)&Ws[k][tc + 4];
            float a[8] = {a0.x, a0.y, a0.z, a0.w, a1.x, a1.y, a1.z, a1.w};
            float b[8] = {b0.x, b0.y, b0.z, b0.w, b1.x, b1.y, b1.z, b1.w};
#pragma unroll
            for (int i = 0; i < 8; ++i)
#pragma unroll
                for (int j = 0; j < 8; ++j)
                    acc[i][j] += a[i] * b[j];
        }
        __syncthreads();
    }
#pragma unroll
    for (int i = 0; i < 8; ++i) {
        int row = by + tr + i;
        if (row < M) {
            *(float4*)(C + (size_t)row * Ncol + bx + tc)     = make_float4(acc[i][0], acc[i][1], acc[i][2], acc[i][3]);
            *(float4*)(C + (size_t)row * Ncol + bx + tc + 4) = make_float4(acc[i][4], acc[i][5], acc[i][6], acc[i][7]);
    }
    }
}

// ---------------- losses ----------------
// warp per row: cos(REX[row], X[row]) over 128 dims; masked (1-cos) accumulated.
__global__ void passloss_k(const float* __restrict__ REX, const float* __restrict__ X,
                           const unsigned char* __restrict__ m, float* __restrict__ acc) {
    int warp = threadIdx.x >> 5, lane = threadIdx.x & 31;
    int row = blockIdx.x * 8 + warp;
    float contrib = 0.f;
    if (row < NNODES) {
        float4 a = ((const float4*)(REX + (size_t)row * D_IN))[lane];
        float4 b = ((const float4*)(X   + (size_t)row * D_IN))[lane];
        float dot = a.x * b.x + a.y * b.y + a.z * b.z + a.w * b.w;
        float na  = a.x * a.x + a.y * a.y + a.z * a.z + a.w * a.w;
        float nb  = b.x * b.x + b.y * b.y + b.z * b.z + b.w * b.w;
#pragma unroll
        for (int o = 16; o; o >>= 1) {
            dot += __shfl_down_sync(0xffffffffu, dot, o);
            na  += __shfl_down_sync(0xffffffffu, na , o);
            nb  += __shfl_down_sync(0xffffffffu, nb , o);
        }
        if (lane == 0 && m[row]) {
            float c = dot / (fmaxf(sqrtf(na), 1e-12f) * fmaxf(sqrtf(nb), 1e-12f));
            contrib = 1.f - c;
        }
    }
    __shared__ float s[8];
    if (lane == 0) s[warp] = contrib;
    __syncthreads();
    if (threadIdx.x == 0) {
        float t = 0.f;
#pragma unroll
        for (int j = 0; j < 8; ++j) t += s[j];
        atomicAdd(acc, t);
    }
}

__global__ void cl_k(const float* __restrict__ A, const float* __restrict__ B, float* __restrict__ acc) {
    int warp = threadIdx.x >> 5, lane = threadIdx.x & 31;
    int row = blockIdx.x * 8 + warp;
    float contrib = 0.f;
    if (row < NNODES) {
        float4 a = ((const float4*)(A + (size_t)row * D_IN))[lane];
        float4 b = ((const float4*)(B + (size_t)row * D_IN))[lane];
        float dot = a.x * b.x + a.y * b.y + a.z * b.z + a.w * b.w;
        float na  = a.x * a.x + a.y * a.y + a.z * a.z + a.w * a.w;
        float nb  = b.x * b.x + b.y * b.y + b.z * b.z + b.w * b.w;
#pragma unroll
        for (int o = 16; o; o >>= 1) {
            dot += __shfl_down_sync(0xffffffffu, dot, o);
            na  += __shfl_down_sync(0xffffffffu, na , o);
            nb  += __shfl_down_sync(0xffffffffu, nb , o);
        }
        if (lane == 0) {
            float c = dot / (fmaxf(sqrtf(na), 1e-12f) * fmaxf(sqrtf(nb), 1e-12f));
            contrib = 1.f - c;
        }
    }
    __shared__ float s[8];
    if (lane == 0) s[warp] = contrib;
    __syncthreads();
    if (threadIdx.x == 0) {
        float t = 0.f;
#pragma unroll
        for (int j = 0; j < 8; ++j) t += s[j];
        atomicAdd(acc, t);
    }
}

__global__ void final_k(float* __restrict__ out) {
    out[0] = g_acc[0] / g_acc[3] + g_acc[1] / g_acc[4] + 0.1f * (g_acc[2] / (float)NNODES);
}

// ---------------- host orchestration ----------------
static void layer(const float* Xin, int Din,
                  const float* w1, const float* bg, const float* bb,
                  const float* w2, int Dout,
                  const float* ng, const float* nb,
                  float* OUT, const unsigned char* maskOrNull,
                  const int* src, const int* dst,
                  float* agg, float* T, float* V, float* stats,
                  float* sc1, float* sh1, float* sc2, float* sh2) {
    // agg = X, then agg[dst] += X[src]
    size_t n4 = (size_t)NNODES * Din / 4;
    copy_k<<<(unsigned)((n4 + 255) / 256), 256>>>(Xin, agg, n4);
    int d4 = Din / 4;
    dim3 sb(d4, 256 / d4);
    scatter_k<<<(NKEEP + sb.y - 1) / sb.y, sb>>>(Xin, agg, src, dst, d4);
    // T = agg @ w1  [N, 512]
    dim3 g1(D_HID / 128, (NNODES + 127) / 128);
    sgemm_k<false><<<g1, 256>>>(agg, w1, T, NNODES, Din, D_HID, nullptr, nullptr);
    // BN(T) stats -> sc1/sh1 (bg, bb)
    cudaMemsetAsync(stats, 0, 2 * D_HID * sizeof(float));
    colstats_k<<<dim3(D_HID / 32, (NNODES + 511) / 512), dim3(32, 8)>>>(T, D_HID, stats, stats + D_HID);
    scaleshift_k<<<(D_HID + 255) / 256, 256>>>(stats, stats + D_HID, bg, bb, sc1, sh1, D_HID);
    // V = relu(BN(T)) @ w2   [N, Dout]  (BN+relu fused into A load)
    dim3 g2(Dout / 128, (NNODES + 127) / 128);
    sgemm_k<true><<<g2, 256>>>(T, w2, V, NNODES, D_HID, Dout, sc1, sh1);
    // BN(V) stats -> sc2/sh2 (ng, nb)
    cudaMemsetAsync(stats, 0, 2 * D_HID * sizeof(float));
    colstats_k<<<dim3(Dout / 32, (NNODES + 511) / 512), dim3(32, 8)>>>(V, Dout, stats, stats + D_HID);
    scaleshift_k<<<(Dout + 255) / 256, 256>>>(stats, stats + D_HID, ng, nb, sc2, sh2, Dout);
    // OUT = relu(BN(V)) (+ optional row mask for re_h)
    int cshift = (Dout == 256) ? 8 : 7;
    size_t nt = (size_t)NNODES * Dout;
    postbn_k<<<(unsigned)((nt + 255) / 256), 256>>>(V, OUT, sc2, sh2, maskOrNull, Dout, cshift);
}

extern "C" void kernel_launch(void* const* d_in, const int* in_sizes, int n_in,
                              void* d_out, int out_size) {
    const float* x = (const float*)d_in[0];
    const int* e1raw = (const int*)d_in[1];
    const int* e2raw = (const int*)d_in[2];
    const unsigned char* m1raw = (const unsigned char*)d_in[3];
    const unsigned char* m2raw = (const unsigned char*)d_in[4];
    // d_in[5] = batch : unused (pooled output is discarded by the reference)
    const float* e0_w1 = (const float*)d_in[6];
    const float* e0_w2 = (const float*)d_in[7];
    const float* e0_bg = (const float*)d_in[8];
    const float* e0_bb = (const float*)d_in[9];
    const float* e0_ng = (const float*)d_in[10];
    const float* e0_nb = (const float*)d_in[11];
    const float* e1_w1 = (const float*)d_in[12];
    const float* e1_w2 = (const float*)d_in[13];
    const float* e1_bg = (const float*)d_in[14];
    const float* e1_bb = (const float*)d_in[15];
    const float* e1_ng = (const float*)d_in[16];
    const float* e1_nb = (const float*)d_in[17];
    const float* dw1   = (const float*)d_in[18];
    const float* dw2   = (const float*)d_in[19];
    const float* dbg   = (const float*)d_in[20];
    const float* dbb   = (const float*)d_in[21];
    const float* dng   = (const float*)d_in[22];
    const float* dnb   = (const float*)d_in[23];
    float* out = (float*)d_out;

    // resolve scratch addresses (not a stream op; capture-safe)
    float *p_x1, *p_agg, *p_T, *p_V, *p_HA, *p_HB, *p_REX1, *p_REX2;
    float *p_stats, *p_sc1, *p_sh1, *p_sc2, *p_sh2, *p_acc;
    int *p_src1, *p_dst1, *p_src2, *p_dst2, *p_flags;
    unsigned char *p_mA, *p_mB;
    cudaGetSymbolAddress((void**)&p_x1,   g_x1);
    cudaGetSymbolAddress((void**)&p_agg,  g_agg);
    cudaGetSymbolAddress((void**)&p_T,    g_T);
    cudaGetSymbolAddress((void**)&p_V,    g_V);
    cudaGetSymbolAddress((void**)&p_HA,   g_HA);
    cudaGetSymbolAddress((void**)&p_HB,   g_HB);
    cudaGetSymbolAddress((void**)&p_REX1, g_REX1);
    cudaGetSymbolAddress((void**)&p_REX2, g_REX2);
    cudaGetSymbolAddress((void**)&p_stats,g_stats);
    cudaGetSymbolAddress((void**)&p_sc1,  g_sc1);
    cudaGetSymbolAddress((void**)&p_sh1,  g_sh1);
    cudaGetSymbolAddress((void**)&p_sc2,  g_sc2);
    cudaGetSymbolAddress((void**)&p_sh2,  g_sh2);
    cudaGetSymbolAddress((void**)&p_acc,  g_acc);
    cudaGetSymbolAddress((void**)&p_src1, g_src1);
    cudaGetSymbolAddress((void**)&p_dst1, g_dst1);
    cudaGetSymbolAddress((void**)&p_src2, g_src2);
    cudaGetSymbolAddress((void**)&p_dst2, g_dst2);
    cudaGetSymbolAddress((void**)&p_flags,g_flags);
    cudaGetSymbolAddress((void**)&p_mA,   g_mA);
    cudaGetSymbolAddress((void**)&p_mB,   g_mB);

    cudaMemsetAsync(p_acc, 0, 8 * sizeof(float));

    detect_k<<<1, 32>>>(e1raw, m1raw);
    convedge_k<<<(NKEEP + 255) / 256, 256>>>(e1raw, p_src1, p_dst1);
    convedge_k<<<(NKEEP + 255) / 256, 256>>>(e2raw, p_src2, p_dst2);
    convmask_k<<<(NNODES + 255) / 256, 256>>>(m1raw, p_mA, p_acc + 3);
    convmask_k<<<(NNODES + 255) / 256, 256>>>(m2raw, p_mB, p_acc + 4);

    for (int pass = 0; pass < 2; ++pass) {
        const int* src = pass ? p_src2 : p_src1;
        const int* dst = pass ? p_dst2 : p_dst1;
        const unsigned char* m = pass ? p_mB : p_mA;
        float* REX = pass ? p_REX2 : p_REX1;

        // x1 = where(mask, 0, x)
        size_t nx = (size_t)NNODES * D_IN;
        maskzero_k<<<(unsigned)((nx + 255) / 256), 256>>>(x, p_x1, m);

        // encoder layer 0: x1 -> HA   (128 -> 512 -> 256)
        layer(p_x1, D_IN, e0_w1, e0_bg, e0_bb, e0_w2, D_OUT, e0_ng, e0_nb,
              p_HA, nullptr, src, dst, p_agg, p_T, p_V, p_stats, p_sc1, p_sh1, p_sc2, p_sh2);
        // encoder layer 1: HA -> HB, with re_h mask fused into output
        layer(p_HA, D_OUT, e1_w1, e1_bg, e1_bb, e1_w2, D_OUT, e1_ng, e1_nb,
              p_HB, m, src, dst, p_agg, p_T, p_V, p_stats, p_sc1, p_sh1, p_sc2, p_sh2);
        // decoder: HB -> REX   (256 -> 512 -> 128)
        layer(p_HB, D_OUT, dw1, dbg, dbb, dw2, D_IN, dng, dnb,
              REX, nullptr, src, dst, p_agg, p_T, p_V, p_stats, p_sc1, p_sh1, p_sc2, p_sh2);

        // masked reconstruction loss numerator
        passloss_k<<<(NNODES + 7) / 8, 256>>>(REX, x, m, p_acc + pass);
    }

    cl_k<<<(NNODES + 7) / 8, 256>>>(p_REX2, p_REX1, p_acc + 2);
    final_k<<<1, 1>>>(out);
    (void)in_sizes; (void)n_in; (void)out_size;
}

// round 2
// speedup vs baseline: 2.0254x; 2.0254x over previous
#include <cuda_runtime.h>
#include <stdint.h>
#include <math.h>

// ---------------- problem constants ----------------
#define NNODES 50000
#define NKEEP  320000
#define D_IN   128
#define D_OUT  256
#define D_HID  512
#define BN_EPS 1e-5f

// ---------------- device scratch (static: no runtime allocation) ----------------
__device__ float g_x1  [(size_t)NNODES * D_IN];
__device__ float g_agg [(size_t)NNODES * D_OUT];
__device__ float g_T   [(size_t)NNODES * D_HID];
__device__ float g_V   [(size_t)NNODES * D_OUT];
__device__ float g_HA  [(size_t)NNODES * D_OUT];
__device__ float g_HB  [(size_t)NNODES * D_OUT];
__device__ float g_REX1[(size_t)NNODES * D_IN];
__device__ float g_REX2[(size_t)NNODES * D_IN];
__device__ int   g_src1[NKEEP], g_dst1[NKEEP], g_src2[NKEEP], g_dst2[NKEEP];
__device__ unsigned char g_mA[NNODES], g_mB[NNODES];
__device__ float g_stats[2 * D_HID];                 // colsum | colsumsq
__device__ float g_sc1[D_HID], g_sh1[D_HID];
__device__ float g_sc2[D_HID], g_sh2[D_HID];
__device__ float g_acc[8];                           // 0:loss1 1:loss2 2:cl 3:cnt1 4:cnt2
__device__ int   g_flags[2];                         // 0: edges are int64; 1: mask is 4-byte

// ---------------- input-format detection ----------------
__global__ void detect_k(const int* __restrict__ e1w, const unsigned char* __restrict__ m1b) {
    if (threadIdx.x == 0 && blockIdx.x == 0) {
        int nz = 0;
        for (int i = 0; i < 64; ++i) nz += (e1w[2 * i + 1] != 0);
        g_flags[0] = (nz == 0) ? 1 : 0;   // all high words zero -> int64
        int nzb = 0;
        for (int i = 0; i < 256; ++i) if (i & 3) nzb += (m1b[i] != 0);
        g_flags[1] = (nzb == 0) ? 1 : 0;  // stride-4 zeros -> 4-byte mask
    }
}

__global__ void convedge_k(const int* __restrict__ raw, int* __restrict__ src, int* __restrict__ dst) {
    int e = blockIdx.x * 256 + threadIdx.x;
    if (e >= NKEEP) return;
    if (g_flags[0]) {  // int64: low word of element
        src[e] = raw[2 * e];
        dst[e] = raw[2 * (NKEEP + e)];
    } else {
        src[e] = raw[e];
        dst[e] = raw[NKEEP + e];
    }
}

__global__ void convmask_k(const void* __restrict__ raw, unsigned char* __restrict__ m, float* __restrict__ cnt) {
    int i = blockIdx.x * 256 + threadIdx.x;
    unsigned char v = 0;
    if (i < NNODES) {
        if (g_flags[1]) v = (((const unsigned int*)raw)[i] != 0u);
        else            v = (((const unsigned char*)raw)[i] != 0);
        m[i] = v;
    }
    __shared__ int s[256];
    s[threadIdx.x] = v;
    __syncthreads();
    for (int o = 128; o; o >>= 1) {
        if (threadIdx.x < o) s[threadIdx.x] += s[threadIdx.x + o];
        __syncthreads();
    }
    if (threadIdx.x == 0) atomicAdd(cnt, (float)s[0]);
}

// ---------------- elementwise ----------------
__global__ void maskzero_k(const float* __restrict__ X, float* __restrict__ Y,
                           const unsigned char* __restrict__ m) {
    size_t i = (size_t)blockIdx.x * blockDim.x + threadIdx.x;
    if (i >= (size_t)NNODES * D_IN) return;
    int row = (int)(i >> 7);  // D_IN = 128
    Y[i] = m[row] ? 0.f : X[i];
}

__global__ void copy_k(const float* __restrict__ X, float* __restrict__ Y, size_t n4) {
    size_t i = (size_t)blockIdx.x * blockDim.x + threadIdx.x;
    if (i < n4) ((float4*)Y)[i] = ((const float4*)X)[i];
}

// apply BN scale/shift + relu (+ optional row mask), V -> H
__global__ void postbn_k(const float* __restrict__ V, float* __restrict__ H,
                         const float* __restrict__ sc, const float* __restrict__ sh,
                         const unsigned char* __restrict__ m, int C, int cshift) {
    size_t i = (size_t)blockIdx.x * blockDim.x + threadIdx.x;
    if (i >= (size_t)NNODES * C) return;
    int c = (int)(i & (size_t)(C - 1));
    float v = fmaxf(V[i] * sc[c] + sh[c], 0.f);
    if (m) {
        int row = (int)(i >> cshift);
        if (m[row]) v = 0.f;
    }
    H[i] = v;
}

// ---------------- edge scatter-add: AGG[dst] += X[src] (vector red) ----------------
__global__ void scatter_k(const float* __restrict__ X, float* __restrict__ AGG,
                          const int* __restrict__ src, const int* __restrict__ dst, int d4) {
    int e = blockIdx.x * blockDim.y + threadIdx.y;
    if (e >= NKEEP) return;
    int s = src[e], d = dst[e];
    int c = threadIdx.x;
    float4 v = ((const float4*)X)[(size_t)s * d4 + c];
    float* p = AGG + ((size_t)d * d4 + c) * 4;
    asm volatile("red.global.add.v4.f32 [%0], {%1,%2,%3,%4};"
                 :: "l"(p), "f"(v.x), "f"(v.y), "f"(v.z), "f"(v.w) : "memory");
}

// ---------------- column stats for BN ----------------
__global__ void colstats_k(const float* __restrict__ T, int C,
                           float* __restrict__ sum, float* __restrict__ sq) {
    int col = blockIdx.x * 32 + threadIdx.x;
    int r0 = blockIdx.y * 512;
    int r1 = min(r0 + 512, NNODES);
    float s = 0.f, q = 0.f;
    for (int r = r0 + threadIdx.y; r < r1; r += 8) {
        float v = T[(size_t)r * C + col];
        s += v; q += v * v;
    }
    __shared__ float ss[8][33], qs[8][33];
    ss[threadIdx.y][threadIdx.x] = s;
    qs[threadIdx.y][threadIdx.x] = q;
    __syncthreads();
    if (threadIdx.y == 0) {
#pragma unroll
        for (int j = 1; j < 8; ++j) { s += ss[j][threadIdx.x]; q += qs[j][threadIdx.x]; }
        atomicAdd(&sum[col], s);
        atomicAdd(&sq[col], q);
    }
}

__global__ void scaleshift_k(const float* __restrict__ sum, const float* __restrict__ sq,
                             const float* __restrict__ g, const float* __restrict__ b,
                             float* __restrict__ sc, float* __restrict__ sh, int C) {
    int c = blockIdx.x * blockDim.x + threadIdx.x;
    if (c >= C) return;
    const float invN = 1.f / (float)NNODES;
    float mu  = sum[c] * invN;
    float var = sq[c] * invN - mu * mu;
    float rs  = rsqrtf(var + BN_EPS);
    float s   = g[c] * rs;
    sc[c] = s;
    sh[c] = b[c] - mu * s;
}

// ---------------- tf32 tensor-core GEMM: C[M,Ncol] = A'[M,K] @ W[K,Ncol] ----------------
// TA: A' = relu(A*sc[k]+sh[k]) fused at A-tile load.
// Block 128x128, BK=32, 8 warps; warp tile 64x32 = 4x4 m16n8k8 fragments.
__device__ __forceinline__ float to_tf32(float x) {
    uint32_t u;
    asm("cvt.rna.tf32.f32 %0, %1;" : "=r"(u) : "f"(x));
    return __uint_as_float(u);
}

template <bool TA>
__global__ void __launch_bounds__(256, 2)
mmagemm_k(const float* __restrict__ A, const float* __restrict__ W, float* __restrict__ C,
          int M, int K, int Ncol, const float* __restrict__ sc, const float* __restrict__ sh) {
    __shared__ float As[128][36];   // stride 36: fragment reads conflict-free
    __shared__ float Bs[32][136];   // stride 136: fragment reads conflict-free
    const int tid  = threadIdx.x;
    const int wid  = tid >> 5, lane = tid & 31;
    const int warpM = wid & 1, warpN = wid >> 1;
    const int by = blockIdx.y * 128, bx = blockIdx.x * 128;
    const int lq = lane >> 2, lr = lane & 3;   // lane/4, lane%4

    float acc[4][4][4];
#pragma unroll
    for (int i = 0; i < 4; ++i)
#pragma unroll
        for (int j = 0; j < 4; ++j)
#pragma unroll
            for (int r = 0; r < 4; ++r) acc[i][j][r] = 0.f;

    for (int kb = 0; kb < K; kb += 32) {
        // --- load A tile: 128x32, 4 float4 per thread, fused BN+relu+tf32 ---
#pragma unroll
        for (int it = 0; it < 4; ++it) {
            int r = (tid >> 3) + it * 32;
            int c = (tid & 7) * 4;
            int grow = by + r;
            float4 v = make_float4(0.f, 0.f, 0.f, 0.f);
            if (grow < M) v = *(const float4*)(A + (size_t)grow * K + kb + c);
            if (TA) {
                int k0 = kb + c;
                v.x = fmaxf(v.x * sc[k0 + 0] + sh[k0 + 0], 0.f);
                v.y = fmaxf(v.y * sc[k0 + 1] + sh[k0 + 1], 0.f);
                v.z = fmaxf(v.z * sc[k0 + 2] + sh[k0 + 2], 0.f);
                v.w = fmaxf(v.w * sc[k0 + 3] + sh[k0 + 3], 0.f);
            }
            As[r][c + 0] = to_tf32(v.x);
            As[r][c + 1] = to_tf32(v.y);
            As[r][c + 2] = to_tf32(v.z);
            As[r][c + 3] = to_tf32(v.w);
        }
        // --- load B tile: 32x128, 4 float4 per thread ---
#pragma unroll
        for (int it = 0; it < 4; ++it) {
            int kr = (tid >> 5) + it * 8;
            int c = lane * 4;
            float4 v = *(const float4*)(W + (size_t)(kb + kr) * Ncol + bx + c);
            Bs[kr][c + 0] = to_tf32(v.x);
            Bs[kr][c + 1] = to_tf32(v.y);
            Bs[kr][c + 2] = to_tf32(v.z);
            Bs[kr][c + 3] = to_tf32(v.w);
        }
        __syncthreads();

#pragma unroll
        for (int k8 = 0; k8 < 4; ++k8) {
            const int krow = k8 * 8;
            uint32_t af[4][4], bf[4][2];
#pragma unroll
            for (int mt = 0; mt < 4; ++mt) {
                int rm = warpM * 64 + mt * 16;
                af[mt][0] = __float_as_uint(As[rm + lq    ][krow + lr    ]);
                af[mt][1] = __float_as_uint(As[rm + 8 + lq][krow + lr    ]);
                af[mt][2] = __float_as_uint(As[rm + lq    ][krow + 4 + lr]);
                af[mt][3] = __float_as_uint(As[rm + 8 + lq][krow + 4 + lr]);
            }
#pragma unroll
            for (int nt = 0; nt < 4; ++nt) {
                int cn = warpN * 32 + nt * 8 + lq;
                bf[nt][0] = __float_as_uint(Bs[krow + lr    ][cn]);
                bf[nt][1] = __float_as_uint(Bs[krow + 4 + lr][cn]);
            }
#pragma unroll
            for (int mt = 0; mt < 4; ++mt)
#pragma unroll
                for (int nt = 0; nt < 4; ++nt) {
                    asm volatile(
                        "mma.sync.aligned.m16n8k8.row.col.f32.tf32.tf32.f32 "
                        "{%0,%1,%2,%3}, {%4,%5,%6,%7}, {%8,%9}, {%0,%1,%2,%3};"
                        : "+f"(acc[mt][nt][0]), "+f"(acc[mt][nt][1]),
                          "+f"(acc[mt][nt][2]), "+f"(acc[mt][nt][3])
                        : "r"(af[mt][0]), "r"(af[mt][1]), "r"(af[mt][2]), "r"(af[mt][3]),
                          "r"(bf[nt][0]), "r"(bf[nt][1]));
                }
        }
        __syncthreads();
    }

    // --- store C: per fragment, rows r0/r0+8, cols 2 consecutive ---
#pragma unroll
    for (int mt = 0; mt < 4; ++mt) {
        int r0 = by + warpM * 64 + mt * 16 + lq;
        int r1 = r0 + 8;
#pragma unroll
        for (int nt = 0; nt < 4; ++nt) {
            int c0 = bx + warpN * 32 + nt * 8 + lr * 2;
            if (r0 < M) *(float2*)(C + (size_t)r0 * Ncol + c0) = make_float2(acc[mt][nt][0], acc[mt][nt][1]);
            if (r1 < M) *(float2*)(C + (size_t)r1 * Ncol + c0) = make_float2(acc[mt][nt][2], acc[mt][nt][3]);
        }
    }
}

// ---------------- losses ----------------
__global__ void passloss_k(const float* __restrict__ REX, const float* __restrict__ X,
                           const unsigned char* __restrict__ m, float* __restrict__ acc) {
    int warp = threadIdx.x >> 5, lane = threadIdx.x & 31;
    int row = blockIdx.x * 8 + warp;
    float contrib = 0.f;
    if (row < NNODES) {
        float4 a = ((const float4*)(REX + (size_t)row * D_IN))[lane];
        float4 b = ((const float4*)(X   + (size_t)row * D_IN))[lane];
        float dot = a.x * b.x + a.y * b.y + a.z * b.z + a.w * b.w;
        float na  = a.x * a.x + a.y * a.y + a.z * a.z + a.w * a.w;
        float nb  = b.x * b.x + b.y * b.y + b.z * b.z + b.w * b.w;
#pragma unroll
        for (int o = 16; o; o >>= 1) {
            dot += __shfl_down_sync(0xffffffffu, dot, o);
            na  += __shfl_down_sync(0xffffffffu, na , o);
            nb  += __shfl_down_sync(0xffffffffu, nb , o);
        }
        if (lane == 0 && m[row]) {
            float c = dot / (fmaxf(sqrtf(na), 1e-12f) * fmaxf(sqrtf(nb), 1e-12f));
            contrib = 1.f - c;
        }
    }
    __shared__ float s[8];
    if (lane == 0) s[warp] = contrib;
    __syncthreads();
    if (threadIdx.x == 0) {
        float t = 0.f;
#pragma unroll
        for (int j = 0; j < 8; ++j) t += s[j];
        atomicAdd(acc, t);
    }
}

__global__ void cl_k(const float* __restrict__ A, const float* __restrict__ B, float* __restrict__ acc) {
    int warp = threadIdx.x >> 5, lane = threadIdx.x & 31;
    int row = blockIdx.x * 8 + warp;
    float contrib = 0.f;
    if (row < NNODES) {
        float4 a = ((const float4*)(A + (size_t)row * D_IN))[lane];
        float4 b = ((const float4*)(B + (size_t)row * D_IN))[lane];
        float dot = a.x * b.x + a.y * b.y + a.z * b.z + a.w * b.w;
        float na  = a.x * a.x + a.y * a.y + a.z * a.z + a.w * a.w;
        float nb  = b.x * b.x + b.y * b.y + b.z * b.z + b.w * b.w;
#pragma unroll
        for (int o = 16; o; o >>= 1) {
            dot += __shfl_down_sync(0xffffffffu, dot, o);
            na  += __shfl_down_sync(0xffffffffu, na , o);
            nb  += __shfl_down_sync(0xffffffffu, nb , o);
        }
        if (lane == 0) {
            float c = dot / (fmaxf(sqrtf(na), 1e-12f) * fmaxf(sqrtf(nb), 1e-12f));
            contrib = 1.f - c;
        }
    }
    __shared__ float s[8];
    if (lane == 0) s[warp] = contrib;
    __syncthreads();
    if (threadIdx.x == 0) {
        float t = 0.f;
#pragma unroll
        for (int j = 0; j < 8; ++j) t += s[j];
        atomicAdd(acc, t);
    }
}

__global__ void final_k(float* __restrict__ out) {
    out[0] = g_acc[0] / g_acc[3] + g_acc[1] / g_acc[4] + 0.1f * (g_acc[2] / (float)NNODES);
}

// ---------------- host orchestration ----------------
static void layer(const float* Xin, int Din,
                  const float* w1, const float* bg, const float* bb,
                  const float* w2, int Dout,
                  const float* ng, const float* nb,
                  float* OUT, const unsigned char* maskOrNull,
                  const int* src, const int* dst,
                  float* agg, float* T, float* V, float* stats,
                  float* sc1, float* sh1, float* sc2, float* sh2) {
    // agg = X, then agg[dst] += X[src]
    size_t n4 = (size_t)NNODES * Din / 4;
    copy_k<<<(unsigned)((n4 + 255) / 256), 256>>>(Xin, agg, n4);
    int d4 = Din / 4;
    dim3 sb(d4, 256 / d4);
    scatter_k<<<(NKEEP + sb.y - 1) / sb.y, sb>>>(Xin, agg, src, dst, d4);
    // T = agg @ w1  [N, 512]
    dim3 g1(D_HID / 128, (NNODES + 127) / 128);
    mmagemm_k<false><<<g1, 256>>>(agg, w1, T, NNODES, Din, D_HID, nullptr, nullptr);
    // BN(T) stats -> sc1/sh1 (bg, bb)
    cudaMemsetAsync(stats, 0, 2 * D_HID * sizeof(float));
    colstats_k<<<dim3(D_HID / 32, (NNODES + 511) / 512), dim3(32, 8)>>>(T, D_HID, stats, stats + D_HID);
    scaleshift_k<<<(D_HID + 255) / 256, 256>>>(stats, stats + D_HID, bg, bb, sc1, sh1, D_HID);
    // V = relu(BN(T)) @ w2   [N, Dout]  (BN+relu fused into A load)
    dim3 g2(Dout / 128, (NNODES + 127) / 128);
    mmagemm_k<true><<<g2, 256>>>(T, w2, V, NNODES, D_HID, Dout, sc1, sh1);
    // BN(V) stats -> sc2/sh2 (ng, nb)
    cudaMemsetAsync(stats, 0, 2 * D_HID * sizeof(float));
    colstats_k<<<dim3(Dout / 32, (NNODES + 511) / 512), dim3(32, 8)>>>(V, Dout, stats, stats + D_HID);
    scaleshift_k<<<(Dout + 255) / 256, 256>>>(stats, stats + D_HID, ng, nb, sc2, sh2, Dout);
    // OUT = relu(BN(V)) (+ optional row mask for re_h)
    int cshift = (Dout == 256) ? 8 : 7;
    size_t nt = (size_t)NNODES * Dout;
    postbn_k<<<(unsigned)((nt + 255) / 256), 256>>>(V, OUT, sc2, sh2, maskOrNull, Dout, cshift);
}

extern "C" void kernel_launch(void* const* d_in, const int* in_sizes, int n_in,
                              void* d_out, int out_size) {
    const float* x = (const float*)d_in[0];
    const int* e1raw = (const int*)d_in[1];
    const int* e2raw = (const int*)d_in[2];
    const unsigned char* m1raw = (const unsigned char*)d_in[3];
    const unsigned char* m2raw = (const unsigned char*)d_in[4];
    // d_in[5] = batch : unused (pooled output is discarded by the reference)
    const float* e0_w1 = (const float*)d_in[6];
    const float* e0_w2 = (const float*)d_in[7];
    const float* e0_bg = (const float*)d_in[8];
    const float* e0_bb = (const float*)d_in[9];
    const float* e0_ng = (const float*)d_in[10];
    const float* e0_nb = (const float*)d_in[11];
    const float* e1_w1 = (const float*)d_in[12];
    const float* e1_w2 = (const float*)d_in[13];
    const float* e1_bg = (const float*)d_in[14];
    const float* e1_bb = (const float*)d_in[15];
    const float* e1_ng = (const float*)d_in[16];
    const float* e1_nb = (const float*)d_in[17];
    const float* dw1   = (const float*)d_in[18];
    const float* dw2   = (const float*)d_in[19];
    const float* dbg   = (const float*)d_in[20];
    const float* dbb   = (const float*)d_in[21];
    const float* dng   = (const float*)d_in[22];
    const float* dnb   = (const float*)d_in[23];
    float* out = (float*)d_out;

    float *p_x1, *p_agg, *p_T, *p_V, *p_HA, *p_HB, *p_REX1, *p_REX2;
    float *p_stats, *p_sc1, *p_sh1, *p_sc2, *p_sh2, *p_acc;
    int *p_src1, *p_dst1, *p_src2, *p_dst2, *p_flags;
    unsigned char *p_mA, *p_mB;
    cudaGetSymbolAddress((void**)&p_x1,   g_x1);
    cudaGetSymbolAddress((void**)&p_agg,  g_agg);
    cudaGetSymbolAddress((void**)&p_T,    g_T);
    cudaGetSymbolAddress((void**)&p_V,    g_V);
    cudaGetSymbolAddress((void**)&p_HA,   g_HA);
    cudaGetSymbolAddress((void**)&p_HB,   g_HB);
    cudaGetSymbolAddress((void**)&p_REX1, g_REX1);
    cudaGetSymbolAddress((void**)&p_REX2, g_REX2);
    cudaGetSymbolAddress((void**)&p_stats,g_stats);
    cudaGetSymbolAddress((void**)&p_sc1,  g_sc1);
    cudaGetSymbolAddress((void**)&p_sh1,  g_sh1);
    cudaGetSymbolAddress((void**)&p_sc2,  g_sc2);
    cudaGetSymbolAddress((void**)&p_sh2,  g_sh2);
    cudaGetSymbolAddress((void**)&p_acc,  g_acc);
    cudaGetSymbolAddress((void**)&p_src1, g_src1);
    cudaGetSymbolAddress((void**)&p_dst1, g_dst1);
    cudaGetSymbolAddress((void**)&p_src2, g_src2);
    cudaGetSymbolAddress((void**)&p_dst2, g_dst2);
    cudaGetSymbolAddress((void**)&p_flags,g_flags);
    cudaGetSymbolAddress((void**)&p_mA,   g_mA);
    cudaGetSymbolAddress((void**)&p_mB,   g_mB);

    cudaMemsetAsync(p_acc, 0, 8 * sizeof(float));

    detect_k<<<1, 32>>>(e1raw, m1raw);
    convedge_k<<<(NKEEP + 255) / 256, 256>>>(e1raw, p_src1, p_dst1);
    convedge_k<<<(NKEEP + 255) / 256, 256>>>(e2raw, p_src2, p_dst2);
    convmask_k<<<(NNODES + 255) / 256, 256>>>(m1raw, p_mA, p_acc + 3);
    convmask_k<<<(NNODES + 255) / 256, 256>>>(m2raw, p_mB, p_acc + 4);

    for (int pass = 0; pass < 2; ++pass) {
        const int* src = pass ? p_src2 : p_src1;
        const int* dst = pass ? p_dst2 : p_dst1;
        const unsigned char* m = pass ? p_mB : p_mA;
        float* REX = pass ? p_REX2 : p_REX1;

        size_t nx = (size_t)NNODES * D_IN;
        maskzero_k<<<(unsigned)((nx + 255) / 256), 256>>>(x, p_x1, m);

        layer(p_x1, D_IN, e0_w1, e0_bg, e0_bb, e0_w2, D_OUT, e0_ng, e0_nb,
              p_HA, nullptr, src, dst, p_agg, p_T, p_V, p_stats, p_sc1, p_sh1, p_sc2, p_sh2);
        layer(p_HA, D_OUT, e1_w1, e1_bg, e1_bb, e1_w2, D_OUT, e1_ng, e1_nb,
              p_HB, m, src, dst, p_agg, p_T, p_V, p_stats, p_sc1, p_sh1, p_sc2, p_sh2);
        layer(p_HB, D_OUT, dw1, dbg, dbb, dw2, D_IN, dng, dnb,
              REX, nullptr, src, dst, p_agg, p_T, p_V, p_stats, p_sc1, p_sh1, p_sc2, p_sh2);

        passloss_k<<<(NNODES + 7) / 8, 256>>>(REX, x, m, p_acc + pass);
    }

    cl_k<<<(NNODES + 7) / 8, 256>>>(p_REX2, p_REX1, p_acc + 2);
    final_k<<<1, 1>>>(out);
    (void)in_sizes; (void)n_in; (void)out_size;
}

// round 3
// speedup vs baseline: 2.7513x; 1.3584x over previous
#include <cuda_runtime.h>
#include <cuda_bf16.h>
#include <stdint.h>
#include <math.h>

// ---------------- problem constants ----------------
#define NNODES 50000
#define NKEEP  320000
#define D_IN   128
#define D_OUT  256
#define D_HID  512
#define BN_EPS 1e-5f

// ---------------- device scratch (static: no runtime allocation) ----------------
__device__ float g_x1  [(size_t)NNODES * D_IN];
__device__ float g_agg [(size_t)NNODES * D_OUT];
__device__ float g_T   [(size_t)NNODES * D_HID];
__device__ float g_V   [(size_t)NNODES * D_OUT];
__device__ float g_HA  [(size_t)NNODES * D_OUT];
__device__ float g_HB  [(size_t)NNODES * D_OUT];
__device__ float g_REX1[(size_t)NNODES * D_IN];
__device__ float g_REX2[(size_t)NNODES * D_IN];
__device__ __nv_bfloat16 g_wb[655360];               // all 6 weights in bf16
__device__ int   g_src1[NKEEP], g_dst1[NKEEP], g_src2[NKEEP], g_dst2[NKEEP];
__device__ unsigned char g_mA[NNODES], g_mB[NNODES];
__device__ float g_stats[2 * D_HID];                 // colsum | colsumsq
__device__ float g_sc1[D_HID], g_sh1[D_HID];
__device__ float g_sc2[D_HID], g_sh2[D_HID];
__device__ float g_acc[8];                           // 0:loss1 1:loss2 2:cl 3:cnt1 4:cnt2
__device__ int   g_flags[2];                         // 0: edges int64; 1: mask 4-byte

// ---------------- input-format detection ----------------
__global__ void detect_k(const int* __restrict__ e1w, const unsigned char* __restrict__ m1b) {
    if (threadIdx.x == 0 && blockIdx.x == 0) {
        int nz = 0;
        for (int i = 0; i < 64; ++i) nz += (e1w[2 * i + 1] != 0);
        g_flags[0] = (nz == 0) ? 1 : 0;
        int nzb = 0;
        for (int i = 0; i < 256; ++i) if (i & 3) nzb += (m1b[i] != 0);
        g_flags[1] = (nzb == 0) ? 1 : 0;
    }
}

__global__ void convedge_k(const int* __restrict__ raw, int* __restrict__ src, int* __restrict__ dst) {
    int e = blockIdx.x * 256 + threadIdx.x;
    if (e >= NKEEP) return;
    if (g_flags[0]) { src[e] = raw[2 * e]; dst[e] = raw[2 * (NKEEP + e)]; }
    else            { src[e] = raw[e];     dst[e] = raw[NKEEP + e]; }
}

__global__ void convmask_k(const void* __restrict__ raw, unsigned char* __restrict__ m, float* __restrict__ cnt) {
    int i = blockIdx.x * 256 + threadIdx.x;
    unsigned char v = 0;
    if (i < NNODES) {
        if (g_flags[1]) v = (((const unsigned int*)raw)[i] != 0u);
        else            v = (((const unsigned char*)raw)[i] != 0);
        m[i] = v;
    }
    __shared__ int s[256];
    s[threadIdx.x] = v;
    __syncthreads();
    for (int o = 128; o; o >>= 1) {
        if (threadIdx.x < o) s[threadIdx.x] += s[threadIdx.x + o];
        __syncthreads();
    }
    if (threadIdx.x == 0) atomicAdd(cnt, (float)s[0]);
}

// ---------------- weight fp32 -> bf16 ----------------
__global__ void convw_k(const float* __restrict__ src, __nv_bfloat16* __restrict__ dst, int n) {
    int i = blockIdx.x * 256 + threadIdx.x;
    if (i < n) dst[i] = __float2bfloat16_rn(src[i]);
}

// ---------------- elementwise ----------------
// x1 = where(mask,0,x); also initializes agg = x1 for layer 0
__global__ void maskzero_k(const float* __restrict__ X, float* __restrict__ Y,
                           float* __restrict__ AGG, const unsigned char* __restrict__ m) {
    size_t i = (size_t)blockIdx.x * blockDim.x + threadIdx.x;
    if (i >= (size_t)NNODES * D_IN) return;
    int row = (int)(i >> 7);
    float v = m[row] ? 0.f : X[i];
    Y[i] = v;
    AGG[i] = v;
}

// apply BN scale/shift + relu (+ optional row mask); dual-write next layer's agg
__global__ void postbn_k(const float* __restrict__ V, float* __restrict__ H,
                         float* __restrict__ AGG,
                         const float* __restrict__ sc, const float* __restrict__ sh,
                         const unsigned char* __restrict__ m, int C, int cshift) {
    size_t i = (size_t)blockIdx.x * blockDim.x + threadIdx.x;
    if (i >= (size_t)NNODES * C) return;
    int c = (int)(i & (size_t)(C - 1));
    float v = fmaxf(V[i] * sc[c] + sh[c], 0.f);
    if (m) {
        int row = (int)(i >> cshift);
        if (m[row]) v = 0.f;
    }
    H[i] = v;
    if (AGG) AGG[i] = v;
}

// ---------------- edge scatter-add: AGG[dst] += X[src] ----------------
__global__ void scatter_k(const float* __restrict__ X, float* __restrict__ AGG,
                          const int* __restrict__ src, const int* __restrict__ dst, int d4) {
    int e = blockIdx.x * blockDim.y + threadIdx.y;
    if (e >= NKEEP) return;
    int s = src[e], d = dst[e];
    int c = threadIdx.x;
    float4 v = ((const float4*)X)[(size_t)s * d4 + c];
    float* p = AGG + ((size_t)d * d4 + c) * 4;
    asm volatile("red.global.add.v4.f32 [%0], {%1,%2,%3,%4};"
                 :: "l"(p), "f"(v.x), "f"(v.y), "f"(v.z), "f"(v.w) : "memory");
}

// ---------------- column stats for BN ----------------
__global__ void colstats_k(const float* __restrict__ T, int C,
                           float* __restrict__ sum, float* __restrict__ sq) {
    int col = blockIdx.x * 32 + threadIdx.x;
    int r0 = blockIdx.y * 512;
    int r1 = min(r0 + 512, NNODES);
    float s = 0.f, q = 0.f;
    for (int r = r0 + threadIdx.y; r < r1; r += 8) {
        float v = T[(size_t)r * C + col];
        s += v; q += v * v;
    }
    __shared__ float ss[8][33], qs[8][33];
    ss[threadIdx.y][threadIdx.x] = s;
    qs[threadIdx.y][threadIdx.x] = q;
    __syncthreads();
    if (threadIdx.y == 0) {
#pragma unroll
        for (int j = 1; j < 8; ++j) { s += ss[j][threadIdx.x]; q += qs[j][threadIdx.x]; }
        atomicAdd(&sum[col], s);
        atomicAdd(&sq[col], q);
    }
}

__global__ void scaleshift_k(const float* __restrict__ sum, const float* __restrict__ sq,
                             const float* __restrict__ g, const float* __restrict__ b,
                             float* __restrict__ sc, float* __restrict__ sh, int C) {
    int c = blockIdx.x * blockDim.x + threadIdx.x;
    if (c >= C) return;
    const float invN = 1.f / (float)NNODES;
    float mu  = sum[c] * invN;
    float var = sq[c] * invN - mu * mu;
    float rs  = rsqrtf(var + BN_EPS);
    float s   = g[c] * rs;
    sc[c] = s;
    sh[c] = b[c] - mu * s;
}

// ---------------- bf16 tensor-core GEMM (double-buffered) ----------------
// C[M,Ncol] = A'[M,K] @ W[K,Ncol]; TA: A' = relu(A*sc+sh) fused at smem store.
// Block 128x128, BK=32, 8 warps (2x4), warp tile 64x32; m16n8k16 bf16 mma.
template <bool TA>
__global__ void __launch_bounds__(256, 2)
bgemm_k(const float* __restrict__ A, const __nv_bfloat16* __restrict__ W, float* __restrict__ C,
        int M, int K, int Ncol, const float* __restrict__ sc, const float* __restrict__ sh) {
    __shared__ __align__(16) __nv_bfloat16 As[2][128][40];
    __shared__ __align__(16) __nv_bfloat16 Bs[2][32][136];
    const int tid  = threadIdx.x;
    const int wid  = tid >> 5, lane = tid & 31;
    const int warpM = wid & 1, warpN = wid >> 1;
    const int by = blockIdx.y * 128, bx = blockIdx.x * 128;
    const int lq = lane >> 2, lr = lane & 3;
    const int ar = tid >> 3;            // 0..31 (+it*32)
    const int ac = (tid & 7) * 4;
    const int bkr = tid >> 4;           // 0..15 (+it*16)
    const int bc  = (tid & 15) * 8;
    const int brow = lane & 15;

    const uint32_t bsBase = (uint32_t)__cvta_generic_to_shared(&Bs[0][0][0]);

    float acc[4][4][4] = {};
    float4 aReg[4];
    uint4  bReg[2];
    const int nT = K >> 5;

    // ---- tile 0 load + store ----
#pragma unroll
    for (int it = 0; it < 4; ++it) {
        int grow = by + ar + it * 32;
        aReg[it] = make_float4(0.f, 0.f, 0.f, 0.f);
        if (grow < M) aReg[it] = *(const float4*)(A + (size_t)grow * K + ac);
    }
#pragma unroll
    for (int it = 0; it < 2; ++it)
        bReg[it] = *(const uint4*)(W + (size_t)(bkr + it * 16) * Ncol + bx + bc);
#pragma unroll
    for (int it = 0; it < 4; ++it) {
        float4 v = aReg[it];
        if (TA) {
            int k0 = ac;
            v.x = fmaxf(v.x * sc[k0 + 0] + sh[k0 + 0], 0.f);
            v.y = fmaxf(v.y * sc[k0 + 1] + sh[k0 + 1], 0.f);
            v.z = fmaxf(v.z * sc[k0 + 2] + sh[k0 + 2], 0.f);
            v.w = fmaxf(v.w * sc[k0 + 3] + sh[k0 + 3], 0.f);
        }
        *(__nv_bfloat162*)&As[0][ar + it * 32][ac]     = __floats2bfloat162_rn(v.x, v.y);
        *(__nv_bfloat162*)&As[0][ar + it * 32][ac + 2] = __floats2bfloat162_rn(v.z, v.w);
    }
#pragma unroll
    for (int it = 0; it < 2; ++it)
        *(uint4*)&Bs[0][bkr + it * 16][bc] = bReg[it];
    __syncthreads();

    for (int t = 0; t < nT; ++t) {
        const int buf = t & 1;
        if (t + 1 < nT) {
            const int kb = (t + 1) * 32;
#pragma unroll
            for (int it = 0; it < 4; ++it) {
                int grow = by + ar + it * 32;
                aReg[it] = make_float4(0.f, 0.f, 0.f, 0.f);
                if (grow < M) aReg[it] = *(const float4*)(A + (size_t)grow * K + kb + ac);
            }
#pragma unroll
            for (int it = 0; it < 2; ++it)
                bReg[it] = *(const uint4*)(W + (size_t)(kb + bkr + it * 16) * Ncol + bx + bc);
        }

#pragma unroll
        for (int k16 = 0; k16 < 2; ++k16) {
            const int kk = k16 * 16;
            uint32_t af[4][4], bf[4][2];
#pragma unroll
            for (int mt = 0; mt < 4; ++mt) {
                int rm = warpM * 64 + mt * 16;
                af[mt][0] = *(const uint32_t*)&As[buf][rm + lq    ][kk + lr * 2];
                af[mt][1] = *(const uint32_t*)&As[buf][rm + 8 + lq][kk + lr * 2];
                af[mt][2] = *(const uint32_t*)&As[buf][rm + lq    ][kk + lr * 2 + 8];
                af[mt][3] = *(const uint32_t*)&As[buf][rm + 8 + lq][kk + lr * 2 + 8];
            }
#pragma unroll
            for (int nt = 0; nt < 4; ++nt) {
                int cn = warpN * 32 + nt * 8;
                uint32_t addr = bsBase + (uint32_t)(((buf * 32 + kk + brow) * 136 + cn) * 2);
                asm volatile("ldmatrix.sync.aligned.m8n8.x2.trans.shared.b16 {%0,%1}, [%2];"
                             : "=r"(bf[nt][0]), "=r"(bf[nt][1]) : "r"(addr));
            }
#pragma unroll
            for (int mt = 0; mt < 4; ++mt)
#pragma unroll
                for (int nt = 0; nt < 4; ++nt) {
                    asm volatile(
                        "mma.sync.aligned.m16n8k16.row.col.f32.bf16.bf16.f32 "
                        "{%0,%1,%2,%3}, {%4,%5,%6,%7}, {%8,%9}, {%0,%1,%2,%3};"
                        : "+f"(acc[mt][nt][0]), "+f"(acc[mt][nt][1]),
                          "+f"(acc[mt][nt][2]), "+f"(acc[mt][nt][3])
                        : "r"(af[mt][0]), "r"(af[mt][1]), "r"(af[mt][2]), "r"(af[mt][3]),
                          "r"(bf[nt][0]), "r"(bf[nt][1]));
                }
        }

        if (t + 1 < nT) {
            const int nb = buf ^ 1;
            const int kb = (t + 1) * 32;
#pragma unroll
            for (int it = 0; it < 4; ++it) {
                float4 v = aReg[it];
                if (TA) {
                    int k0 = kb + ac;
                    v.x = fmaxf(v.x * sc[k0 + 0] + sh[k0 + 0], 0.f);
                    v.y = fmaxf(v.y * sc[k0 + 1] + sh[k0 + 1], 0.f);
                    v.z = fmaxf(v.z * sc[k0 + 2] + sh[k0 + 2], 0.f);
                    v.w = fmaxf(v.w * sc[k0 + 3] + sh[k0 + 3], 0.f);
                }
                *(__nv_bfloat162*)&As[nb][ar + it * 32][ac]     = __floats2bfloat162_rn(v.x, v.y);
                *(__nv_bfloat162*)&As[nb][ar + it * 32][ac + 2] = __floats2bfloat162_rn(v.z, v.w);
            }
#pragma unroll
            for (int it = 0; it < 2; ++it)
                *(uint4*)&Bs[nb][bkr + it * 16][bc] = bReg[it];
            __syncthreads();
        }
    }

    // ---- store C ----
#pragma unroll
    for (int mt = 0; mt < 4; ++mt) {
        int r0 = by + warpM * 64 + mt * 16 + lq;
        int r1 = r0 + 8;
#pragma unroll
        for (int nt = 0; nt < 4; ++nt) {
            int c0 = bx + warpN * 32 + nt * 8 + lr * 2;
            if (r0 < M) *(float2*)(C + (size_t)r0 * Ncol + c0) = make_float2(acc[mt][nt][0], acc[mt][nt][1]);
            if (r1 < M) *(float2*)(C + (size_t)r1 * Ncol + c0) = make_float2(acc[mt][nt][2], acc[mt][nt][3]);
        }
    }
}

// ---------------- losses ----------------
__global__ void passloss_k(const float* __restrict__ REX, const float* __restrict__ X,
                           const unsigned char* __restrict__ m, float* __restrict__ acc) {
    int warp = threadIdx.x >> 5, lane = threadIdx.x & 31;
    int row = blockIdx.x * 8 + warp;
    float contrib = 0.f;
    if (row < NNODES) {
        float4 a = ((const float4*)(REX + (size_t)row * D_IN))[lane];
        float4 b = ((const float4*)(X   + (size_t)row * D_IN))[lane];
        float dot = a.x * b.x + a.y * b.y + a.z * b.z + a.w * b.w;
        float na  = a.x * a.x + a.y * a.y + a.z * a.z + a.w * a.w;
        float nb  = b.x * b.x + b.y * b.y + b.z * b.z + b.w * b.w;
#pragma unroll
        for (int o = 16; o; o >>= 1) {
            dot += __shfl_down_sync(0xffffffffu, dot, o);
            na  += __shfl_down_sync(0xffffffffu, na , o);
            nb  += __shfl_down_sync(0xffffffffu, nb , o);
        }
        if (lane == 0 && m[row]) {
            float c = dot / (fmaxf(sqrtf(na), 1e-12f) * fmaxf(sqrtf(nb), 1e-12f));
            contrib = 1.f - c;
        }
    }
    __shared__ float s[8];
    if (lane == 0) s[warp] = contrib;
    __syncthreads();
    if (threadIdx.x == 0) {
        float t = 0.f;
#pragma unroll
        for (int j = 0; j < 8; ++j) t += s[j];
        atomicAdd(acc, t);
    }
}

__global__ void cl_k(const float* __restrict__ A, const float* __restrict__ B, float* __restrict__ acc) {
    int warp = threadIdx.x >> 5, lane = threadIdx.x & 31;
    int row = blockIdx.x * 8 + warp;
    float contrib = 0.f;
    if (row < NNODES) {
        float4 a = ((const float4*)(A + (size_t)row * D_IN))[lane];
        float4 b = ((const float4*)(B + (size_t)row * D_IN))[lane];
        float dot = a.x * b.x + a.y * b.y + a.z * b.z + a.w * b.w;
        float na  = a.x * a.x + a.y * a.y + a.z * a.z + a.w * a.w;
        float nb  = b.x * b.x + b.y * b.y + b.z * b.z + b.w * b.w;
#pragma unroll
        for (int o = 16; o; o >>= 1) {
            dot += __shfl_down_sync(0xffffffffu, dot, o);
            na  += __shfl_down_sync(0xffffffffu, na , o);
            nb  += __shfl_down_sync(0xffffffffu, nb , o);
        }
        if (lane == 0) {
            float c = dot / (fmaxf(sqrtf(na), 1e-12f) * fmaxf(sqrtf(nb), 1e-12f));
            contrib = 1.f - c;
        }
    }
    __shared__ float s[8];
    if (lane == 0) s[warp] = contrib;
    __syncthreads();
    if (threadIdx.x == 0) {
        float t = 0.f;
#pragma unroll
        for (int j = 0; j < 8; ++j) t += s[j];
        atomicAdd(acc, t);
    }
}

__global__ void final_k(float* __restrict__ out) {
    out[0] = g_acc[0] / g_acc[3] + g_acc[1] / g_acc[4] + 0.1f * (g_acc[2] / (float)NNODES);
}

// ---------------- host orchestration ----------------
// agg must be pre-initialized to Xin by the previous op (dual-write).
static void layer(const float* Xin, int Din,
                  const __nv_bfloat16* w1b, const float* bg, const float* bb,
                  const __nv_bfloat16* w2b, int Dout,
                  const float* ng, const float* nb,
                  float* OUT, float* aggNext, const unsigned char* maskOrNull,
                  const int* src, const int* dst,
                  float* agg, float* T, float* V, float* stats,
                  float* sc1, float* sh1, float* sc2, float* sh2) {
    int d4 = Din / 4;
    dim3 sb(d4, 256 / d4);
    scatter_k<<<(NKEEP + sb.y - 1) / sb.y, sb>>>(Xin, agg, src, dst, d4);
    dim3 g1(D_HID / 128, (NNODES + 127) / 128);
    bgemm_k<false><<<g1, 256>>>(agg, w1b, T, NNODES, Din, D_HID, nullptr, nullptr);
    cudaMemsetAsync(stats, 0, 2 * D_HID * sizeof(float));
    colstats_k<<<dim3(D_HID / 32, (NNODES + 511) / 512), dim3(32, 8)>>>(T, D_HID, stats, stats + D_HID);
    scaleshift_k<<<(D_HID + 255) / 256, 256>>>(stats, stats + D_HID, bg, bb, sc1, sh1, D_HID);
    dim3 g2(Dout / 128, (NNODES + 127) / 128);
    bgemm_k<true><<<g2, 256>>>(T, w2b, V, NNODES, D_HID, Dout, sc1, sh1);
    cudaMemsetAsync(stats, 0, 2 * D_HID * sizeof(float));
    colstats_k<<<dim3(Dout / 32, (NNODES + 511) / 512), dim3(32, 8)>>>(V, Dout, stats, stats + D_HID);
    scaleshift_k<<<(Dout + 255) / 256, 256>>>(stats, stats + D_HID, ng, nb, sc2, sh2, Dout);
    int cshift = (Dout == 256) ? 8 : 7;
    size_t nt = (size_t)NNODES * Dout;
    postbn_k<<<(unsigned)((nt + 255) / 256), 256>>>(V, OUT, aggNext, sc2, sh2, maskOrNull, Dout, cshift);
}

extern "C" void kernel_launch(void* const* d_in, const int* in_sizes, int n_in,
                              void* d_out, int out_size) {
    const float* x = (const float*)d_in[0];
    const int* e1raw = (const int*)d_in[1];
    const int* e2raw = (const int*)d_in[2];
    const unsigned char* m1raw = (const unsigned char*)d_in[3];
    const unsigned char* m2raw = (const unsigned char*)d_in[4];
    // d_in[5] = batch : unused (pooled output discarded by reference)
    const float* e0_w1 = (const float*)d_in[6];
    const float* e0_w2 = (const float*)d_in[7];
    const float* e0_bg = (const float*)d_in[8];
    const float* e0_bb = (const float*)d_in[9];
    const float* e0_ng = (const float*)d_in[10];
    const float* e0_nb = (const float*)d_in[11];
    const float* e1_w1 = (const float*)d_in[12];
    const float* e1_w2 = (const float*)d_in[13];
    const float* e1_bg = (const float*)d_in[14];
    const float* e1_bb = (const float*)d_in[15];
    const float* e1_ng = (const float*)d_in[16];
    const float* e1_nb = (const float*)d_in[17];
    const float* dw1   = (const float*)d_in[18];
    const float* dw2   = (const float*)d_in[19];
    const float* dbg   = (const float*)d_in[20];
    const float* dbb   = (const float*)d_in[21];
    const float* dng   = (const float*)d_in[22];
    const float* dnb   = (const float*)d_in[23];
    float* out = (float*)d_out;

    float *p_x1, *p_agg, *p_T, *p_V, *p_HA, *p_HB, *p_REX1, *p_REX2;
    float *p_stats, *p_sc1, *p_sh1, *p_sc2, *p_sh2, *p_acc;
    int *p_src1, *p_dst1, *p_src2, *p_dst2;
    unsigned char *p_mA, *p_mB;
    __nv_bfloat16* p_wb;
    cudaGetSymbolAddress((void**)&p_x1,   g_x1);
    cudaGetSymbolAddress((void**)&p_agg,  g_agg);
    cudaGetSymbolAddress((void**)&p_T,    g_T);
    cudaGetSymbolAddress((void**)&p_V,    g_V);
    cudaGetSymbolAddress((void**)&p_HA,   g_HA);
    cudaGetSymbolAddress((void**)&p_HB,   g_HB);
    cudaGetSymbolAddress((void**)&p_REX1, g_REX1);
    cudaGetSymbolAddress((void**)&p_REX2, g_REX2);
    cudaGetSymbolAddress((void**)&p_stats,g_stats);
    cudaGetSymbolAddress((void**)&p_sc1,  g_sc1);
    cudaGetSymbolAddress((void**)&p_sh1,  g_sh1);
    cudaGetSymbolAddress((void**)&p_sc2,  g_sc2);
    cudaGetSymbolAddress((void**)&p_sh2,  g_sh2);
    cudaGetSymbolAddress((void**)&p_acc,  g_acc);
    cudaGetSymbolAddress((void**)&p_src1, g_src1);
    cudaGetSymbolAddress((void**)&p_dst1, g_dst1);
    cudaGetSymbolAddress((void**)&p_src2, g_src2);
    cudaGetSymbolAddress((void**)&p_dst2, g_dst2);
    cudaGetSymbolAddress((void**)&p_mA,   g_mA);
    cudaGetSymbolAddress((void**)&p_mB,   g_mB);
    cudaGetSymbolAddress((void**)&p_wb,   g_wb);

    // bf16 weight table offsets
    __nv_bfloat16* wb_e0w1 = p_wb + 0;
    __nv_bfloat16* wb_e0w2 = p_wb + 65536;
    __nv_bfloat16* wb_e1w1 = p_wb + 196608;
    __nv_bfloat16* wb_e1w2 = p_wb + 327680;
    __nv_bfloat16* wb_dw1  = p_wb + 458752;
    __nv_bfloat16* wb_dw2  = p_wb + 589824;

    cudaMemsetAsync(p_acc, 0, 8 * sizeof(float));

    detect_k<<<1, 32>>>(e1raw, m1raw);
    convedge_k<<<(NKEEP + 255) / 256, 256>>>(e1raw, p_src1, p_dst1);
    convedge_k<<<(NKEEP + 255) / 256, 256>>>(e2raw, p_src2, p_dst2);
    convmask_k<<<(NNODES + 255) / 256, 256>>>(m1raw, p_mA, p_acc + 3);
    convmask_k<<<(NNODES + 255) / 256, 256>>>(m2raw, p_mB, p_acc + 4);
    convw_k<<<(65536  + 255) / 256, 256>>>(e0_w1, wb_e0w1, 65536);
    convw_k<<<(131072 + 255) / 256, 256>>>(e0_w2, wb_e0w2, 131072);
    convw_k<<<(131072 + 255) / 256, 256>>>(e1_w1, wb_e1w1, 131072);
    convw_k<<<(131072 + 255) / 256, 256>>>(e1_w2, wb_e1w2, 131072);
    convw_k<<<(131072 + 255) / 256, 256>>>(dw1,   wb_dw1,  131072);
    convw_k<<<(65536  + 255) / 256, 256>>>(dw2,   wb_dw2,  65536);

    for (int pass = 0; pass < 2; ++pass) {
        const int* src = pass ? p_src2 : p_src1;
        const int* dst = pass ? p_dst2 : p_dst1;
        const unsigned char* m = pass ? p_mB : p_mA;
        float* REX = pass ? p_REX2 : p_REX1;

        size_t nx = (size_t)NNODES * D_IN;
        maskzero_k<<<(unsigned)((nx + 255) / 256), 256>>>(x, p_x1, p_agg, m);

        // encoder 0: x1 -> HA (agg preset by maskzero; postbn presets agg=HA)
        layer(p_x1, D_IN, wb_e0w1, e0_bg, e0_bb, wb_e0w2, D_OUT, e0_ng, e0_nb,
              p_HA, p_agg, nullptr, src, dst, p_agg, p_T, p_V, p_stats, p_sc1, p_sh1, p_sc2, p_sh2);
        // encoder 1: HA -> HB (masked re_h); postbn presets agg=HB(masked)
        layer(p_HA, D_OUT, wb_e1w1, e1_bg, e1_bb, wb_e1w2, D_OUT, e1_ng, e1_nb,
              p_HB, p_agg, m, src, dst, p_agg, p_T, p_V, p_stats, p_sc1, p_sh1, p_sc2, p_sh2);
        // decoder: HB -> REX
        layer(p_HB, D_OUT, wb_dw1, dbg, dbb, wb_dw2, D_IN, dng, dnb,
              REX, nullptr, nullptr, src, dst, p_agg, p_T, p_V, p_stats, p_sc1, p_sh1, p_sc2, p_sh2);

        passloss_k<<<(NNODES + 7) / 8, 256>>>(REX, x, m, p_acc + pass);
    }

    cl_k<<<(NNODES + 7) / 8, 256>>>(p_REX2, p_REX1, p_acc + 2);
    final_k<<<1, 1>>>(out);
    (void)in_sizes; (void)n_in; (void)out_size;
}

// round 4
// speedup vs baseline: 2.8836x; 1.0481x over previous
#include <cuda_runtime.h>
#include <cuda_bf16.h>
#include <stdint.h>
#include <math.h>

// ---------------- problem constants ----------------
#define NNODES 50000
#define NKEEP  320000
#define D_IN   128
#define D_OUT  256
#define D_HID  512
#define BN_EPS 1e-5f

// ---------------- device scratch (static: no runtime allocation) ----------------
__device__ float g_agg [(size_t)NNODES * D_OUT];
__device__ float g_T   [(size_t)NNODES * D_HID];
__device__ float g_V   [(size_t)NNODES * D_OUT];
__device__ float g_REX1[(size_t)NNODES * D_IN];
__device__ float g_REX2[(size_t)NNODES * D_IN];
__device__ __nv_bfloat16 g_wb[655360];               // all 6 weights in bf16
__device__ int   g_src1[NKEEP], g_dst1[NKEEP], g_src2[NKEEP], g_dst2[NKEEP];
__device__ unsigned char g_mA[NNODES], g_mB[NNODES];
__device__ float g_stats[2 * D_HID];                 // colsum | colsumsq (zero-init; scaleshift re-zeroes)
__device__ float g_sc1[D_HID], g_sh1[D_HID];
__device__ float g_sc2[D_HID], g_sh2[D_HID];
__device__ float g_acc[8];                           // 0:loss1 1:loss2 2:cl 3:cnt1 4:cnt2
__device__ int   g_flags[2];                         // 0: edges int64; 1: mask 4-byte

// ---------------- input-format detection ----------------
__global__ void detect_k(const int* __restrict__ e1w, const unsigned char* __restrict__ m1b) {
    if (threadIdx.x == 0 && blockIdx.x == 0) {
        int nz = 0;
        for (int i = 0; i < 64; ++i) nz += (e1w[2 * i + 1] != 0);
        g_flags[0] = (nz == 0) ? 1 : 0;
        int nzb = 0;
        for (int i = 0; i < 256; ++i) if (i & 3) nzb += (m1b[i] != 0);
        g_flags[1] = (nzb == 0) ? 1 : 0;
    }
}

__global__ void convedge_k(const int* __restrict__ raw, int* __restrict__ src, int* __restrict__ dst) {
    int e = blockIdx.x * 256 + threadIdx.x;
    if (e >= NKEEP) return;
    if (g_flags[0]) { src[e] = raw[2 * e]; dst[e] = raw[2 * (NKEEP + e)]; }
    else            { src[e] = raw[e];     dst[e] = raw[NKEEP + e]; }
}

__global__ void convmask_k(const void* __restrict__ raw, unsigned char* __restrict__ m, float* __restrict__ cnt) {
    int i = blockIdx.x * 256 + threadIdx.x;
    unsigned char v = 0;
    if (i < NNODES) {
        if (g_flags[1]) v = (((const unsigned int*)raw)[i] != 0u);
        else            v = (((const unsigned char*)raw)[i] != 0);
        m[i] = v;
    }
    __shared__ int s[256];
    s[threadIdx.x] = v;
    __syncthreads();
    for (int o = 128; o; o >>= 1) {
        if (threadIdx.x < o) s[threadIdx.x] += s[threadIdx.x + o];
        __syncthreads();
    }
    if (threadIdx.x == 0) atomicAdd(cnt, (float)s[0]);
}

// ---------------- weight fp32 -> bf16 ----------------
__global__ void convw_k(const float* __restrict__ src, __nv_bfloat16* __restrict__ dst, int n) {
    int i = blockIdx.x * 256 + threadIdx.x;
    if (i < n) dst[i] = __float2bfloat16_rn(src[i]);
}

// ---------------- elementwise ----------------
// agg = where(mask,0,x)  (layer-0 self term)
__global__ void maskagg_k(const float* __restrict__ X, float* __restrict__ AGG,
                          const unsigned char* __restrict__ m) {
    size_t i = (size_t)blockIdx.x * blockDim.x + threadIdx.x;
    if (i >= (size_t)NNODES * D_IN) return;
    int row = (int)(i >> 7);
    AGG[i] = m[row] ? 0.f : X[i];
}

// OUT = relu(V*sc+sh), optional row mask (single write: next agg self-term, or REX)
__global__ void postbn_k(const float* __restrict__ V, float* __restrict__ OUT,
                         const float* __restrict__ sc, const float* __restrict__ sh,
                         const unsigned char* __restrict__ m, int C, int cshift) {
    size_t i = (size_t)blockIdx.x * blockDim.x + threadIdx.x;
    if (i >= (size_t)NNODES * C) return;
    int c = (int)(i & (size_t)(C - 1));
    float v = fmaxf(V[i] * sc[c] + sh[c], 0.f);
    if (m) {
        int row = (int)(i >> cshift);
        if (m[row]) v = 0.f;
    }
    OUT[i] = v;
}

// ---------------- fused edge scatter-add: AGG[dst] += f(X[src]) ----------------
// BN: apply relu(x*sc+sh) on gather; MASK: skip edge if mask[src]
template <bool BN, bool MASK>
__global__ void scatter_k(const float* __restrict__ X, float* __restrict__ AGG,
                          const int* __restrict__ src, const int* __restrict__ dst, int d4,
                          const float* __restrict__ sc, const float* __restrict__ sh,
                          const unsigned char* __restrict__ m) {
    int e = blockIdx.x * blockDim.y + threadIdx.y;
    if (e >= NKEEP) return;
    int s = src[e];
    if (MASK && m[s]) return;
    int d = dst[e];
    int c = threadIdx.x;
    float4 v = ((const float4*)X)[(size_t)s * d4 + c];
    if (BN) {
        int k0 = c * 4;
        v.x = fmaxf(v.x * sc[k0 + 0] + sh[k0 + 0], 0.f);
        v.y = fmaxf(v.y * sc[k0 + 1] + sh[k0 + 1], 0.f);
        v.z = fmaxf(v.z * sc[k0 + 2] + sh[k0 + 2], 0.f);
        v.w = fmaxf(v.w * sc[k0 + 3] + sh[k0 + 3], 0.f);
    }
    float* p = AGG + ((size_t)d * d4 + c) * 4;
    asm volatile("red.global.add.v4.f32 [%0], {%1,%2,%3,%4};"
                 :: "l"(p), "f"(v.x), "f"(v.y), "f"(v.z), "f"(v.w) : "memory");
}

// ---------------- BN scale/shift (reads stats, then re-zeroes them) ----------------
__global__ void scaleshift_k(float* __restrict__ sum, float* __restrict__ sq,
                             const float* __restrict__ g, const float* __restrict__ b,
                             float* __restrict__ sc, float* __restrict__ sh, int C) {
    int c = blockIdx.x * blockDim.x + threadIdx.x;
    if (c >= C) return;
    const float invN = 1.f / (float)NNODES;
    float s_ = sum[c], q_ = sq[c];
    sum[c] = 0.f; sq[c] = 0.f;              // ready for next GEMM's accumulation
    float mu  = s_ * invN;
    float var = q_ * invN - mu * mu;
    float rs  = rsqrtf(var + BN_EPS);
    float s   = g[c] * rs;
    sc[c] = s;
    sh[c] = b[c] - mu * s;
}

// ---------------- bf16 tensor-core GEMM (double-buffered, fused stats epilogue) ----
// C[M,Ncol] = A'[M,K] @ W[K,Ncol]; TA: A' = relu(A*sc+sh) fused at smem store.
// Block 128x128, BK=32, 8 warps (2x4), warp tile 64x32; m16n8k16 bf16 mma.
// Epilogue accumulates per-column sum/sumsq of C into ssum/ssq (BN stats).
template <bool TA>
__global__ void __launch_bounds__(256, 2)
bgemm_k(const float* __restrict__ A, const __nv_bfloat16* __restrict__ W, float* __restrict__ C,
        int M, int K, int Ncol, const float* __restrict__ sc, const float* __restrict__ sh,
        float* __restrict__ ssum, float* __restrict__ ssq) {
    __shared__ __align__(16) __nv_bfloat16 As[2][128][40];
    __shared__ __align__(16) __nv_bfloat16 Bs[2][32][136];
    __shared__ float s_sum[128], s_sq[128];
    const int tid  = threadIdx.x;
    const int wid  = tid >> 5, lane = tid & 31;
    const int warpM = wid & 1, warpN = wid >> 1;
    const int by = blockIdx.y * 128, bx = blockIdx.x * 128;
    const int lq = lane >> 2, lr = lane & 3;
    const int ar = tid >> 3;            // 0..31 (+it*32)
    const int ac = (tid & 7) * 4;
    const int bkr = tid >> 4;           // 0..15 (+it*16)
    const int bc  = (tid & 15) * 8;
    const int brow = lane & 15;
    const int aRow = (lane & 7) + ((lane >> 3) & 1) * 8;  // ldmatrix.x4 row-in-tile
    const int aKh  = (lane >> 4) * 8;                     // ldmatrix.x4 k-half

    const uint32_t bsBase = (uint32_t)__cvta_generic_to_shared(&Bs[0][0][0]);
    const uint32_t asBase = (uint32_t)__cvta_generic_to_shared(&As[0][0][0]);

    float acc[4][4][4] = {};
    float4 aReg[4];
    uint4  bReg[2];
    const int nT = K >> 5;

    // ---- tile 0 load + store ----
#pragma unroll
    for (int it = 0; it < 4; ++it) {
        int grow = by + ar + it * 32;
        aReg[it] = make_float4(0.f, 0.f, 0.f, 0.f);
        if (grow < M) aReg[it] = *(const float4*)(A + (size_t)grow * K + ac);
    }
#pragma unroll
    for (int it = 0; it < 2; ++it)
        bReg[it] = *(const uint4*)(W + (size_t)(bkr + it * 16) * Ncol + bx + bc);
#pragma unroll
    for (int it = 0; it < 4; ++it) {
        float4 v = aReg[it];
        if (TA) {
            int k0 = ac;
            v.x = fmaxf(v.x * sc[k0 + 0] + sh[k0 + 0], 0.f);
            v.y = fmaxf(v.y * sc[k0 + 1] + sh[k0 + 1], 0.f);
            v.z = fmaxf(v.z * sc[k0 + 2] + sh[k0 + 2], 0.f);
            v.w = fmaxf(v.w * sc[k0 + 3] + sh[k0 + 3], 0.f);
            if (by + ar + it * 32 >= M) v = make_float4(0.f, 0.f, 0.f, 0.f);
        }
        *(__nv_bfloat162*)&As[0][ar + it * 32][ac]     = __floats2bfloat162_rn(v.x, v.y);
        *(__nv_bfloat162*)&As[0][ar + it * 32][ac + 2] = __floats2bfloat162_rn(v.z, v.w);
    }
#pragma unroll
    for (int it = 0; it < 2; ++it)
        *(uint4*)&Bs[0][bkr + it * 16][bc] = bReg[it];
    __syncthreads();

    for (int t = 0; t < nT; ++t) {
        const int buf = t & 1;
        if (t + 1 < nT) {
            const int kb = (t + 1) * 32;
#pragma unroll
            for (int it = 0; it < 4; ++it) {
                int grow = by + ar + it * 32;
                aReg[it] = make_float4(0.f, 0.f, 0.f, 0.f);
                if (grow < M) aReg[it] = *(const float4*)(A + (size_t)grow * K + kb + ac);
            }
#pragma unroll
            for (int it = 0; it < 2; ++it)
                bReg[it] = *(const uint4*)(W + (size_t)(kb + bkr + it * 16) * Ncol + bx + bc);
        }

#pragma unroll
        for (int k16 = 0; k16 < 2; ++k16) {
            const int kk = k16 * 16;
            uint32_t af[4][4], bf[4][2];
#pragma unroll
            for (int mt = 0; mt < 4; ++mt) {
                int rm = warpM * 64 + mt * 16;
                uint32_t addr = asBase + (uint32_t)(((buf * 128 + rm + aRow) * 40 + kk + aKh) * 2);
                asm volatile("ldmatrix.sync.aligned.m8n8.x4.shared.b16 {%0,%1,%2,%3}, [%4];"
                             : "=r"(af[mt][0]), "=r"(af[mt][1]), "=r"(af[mt][2]), "=r"(af[mt][3])
                             : "r"(addr));
            }
#pragma unroll
            for (int nt = 0; nt < 4; ++nt) {
                int cn = warpN * 32 + nt * 8;
                uint32_t addr = bsBase + (uint32_t)(((buf * 32 + kk + brow) * 136 + cn) * 2);
                asm volatile("ldmatrix.sync.aligned.m8n8.x2.trans.shared.b16 {%0,%1}, [%2];"
                             : "=r"(bf[nt][0]), "=r"(bf[nt][1]) : "r"(addr));
            }
#pragma unroll
            for (int mt = 0; mt < 4; ++mt)
#pragma unroll
                for (int nt = 0; nt < 4; ++nt) {
                    asm volatile(
                        "mma.sync.aligned.m16n8k16.row.col.f32.bf16.bf16.f32 "
                        "{%0,%1,%2,%3}, {%4,%5,%6,%7}, {%8,%9}, {%0,%1,%2,%3};"
                        : "+f"(acc[mt][nt][0]), "+f"(acc[mt][nt][1]),
                          "+f"(acc[mt][nt][2]), "+f"(acc[mt][nt][3])
                        : "r"(af[mt][0]), "r"(af[mt][1]), "r"(af[mt][2]), "r"(af[mt][3]),
                          "r"(bf[nt][0]), "r"(bf[nt][1]));
                }
        }

        if (t + 1 < nT) {
            const int nb = buf ^ 1;
            const int kb = (t + 1) * 32;
#pragma unroll
            for (int it = 0; it < 4; ++it) {
                float4 v = aReg[it];
                if (TA) {
                    int k0 = kb + ac;
                    v.x = fmaxf(v.x * sc[k0 + 0] + sh[k0 + 0], 0.f);
                    v.y = fmaxf(v.y * sc[k0 + 1] + sh[k0 + 1], 0.f);
                    v.z = fmaxf(v.z * sc[k0 + 2] + sh[k0 + 2], 0.f);
                    v.w = fmaxf(v.w * sc[k0 + 3] + sh[k0 + 3], 0.f);
                    if (by + ar + it * 32 >= M) v = make_float4(0.f, 0.f, 0.f, 0.f);
                }
                *(__nv_bfloat162*)&As[nb][ar + it * 32][ac]     = __floats2bfloat162_rn(v.x, v.y);
                *(__nv_bfloat162*)&As[nb][ar + it * 32][ac + 2] = __floats2bfloat162_rn(v.z, v.w);
            }
#pragma unroll
            for (int it = 0; it < 2; ++it)
                *(uint4*)&Bs[nb][bkr + it * 16][bc] = bReg[it];
            __syncthreads();
        }
    }

    // ---- store C ----
#pragma unroll
    for (int mt = 0; mt < 4; ++mt) {
        int r0 = by + warpM * 64 + mt * 16 + lq;
        int r1 = r0 + 8;
#pragma unroll
        for (int nt = 0; nt < 4; ++nt) {
            int c0 = bx + warpN * 32 + nt * 8 + lr * 2;
            if (r0 < M) *(float2*)(C + (size_t)r0 * Ncol + c0) = make_float2(acc[mt][nt][0], acc[mt][nt][1]);
            if (r1 < M) *(float2*)(C + (size_t)r1 * Ncol + c0) = make_float2(acc[mt][nt][2], acc[mt][nt][3]);
        }
    }

    // ---- fused BN stats epilogue: per-column sum / sumsq ----
    // (padded rows contribute exact zeros: A rows >= M are zeroed post-BN)
    for (int i = tid; i < 128; i += 256) { s_sum[i] = 0.f; s_sq[i] = 0.f; }
    __syncthreads();
#pragma unroll
    for (int nt = 0; nt < 4; ++nt) {
        float s0 = 0.f, q0 = 0.f, s1 = 0.f, q1 = 0.f;
#pragma unroll
        for (int mt = 0; mt < 4; ++mt) {
            float a0 = acc[mt][nt][0], a1 = acc[mt][nt][1];
            float a2 = acc[mt][nt][2], a3 = acc[mt][nt][3];
            s0 += a0 + a2; q0 += a0 * a0 + a2 * a2;
            s1 += a1 + a3; q1 += a1 * a1 + a3 * a3;
        }
#pragma unroll
        for (int o = 4; o < 32; o <<= 1) {
            s0 += __shfl_xor_sync(0xffffffffu, s0, o);
            q0 += __shfl_xor_sync(0xffffffffu, q0, o);
            s1 += __shfl_xor_sync(0xffffffffu, s1, o);
            q1 += __shfl_xor_sync(0xffffffffu, q1, o);
        }
        if (lq == 0) {
            int c0 = warpN * 32 + nt * 8 + lr * 2;
            atomicAdd(&s_sum[c0],     s0); atomicAdd(&s_sq[c0],     q0);
            atomicAdd(&s_sum[c0 + 1], s1); atomicAdd(&s_sq[c0 + 1], q1);
        }
    }
    __syncthreads();
    for (int i = tid; i < 128; i += 256) {
        atomicAdd(&ssum[bx + i], s_sum[i]);
        atomicAdd(&ssq[bx + i],  s_sq[i]);
    }
}

// ---------------- losses ----------------
__global__ void passloss_k(const float* __restrict__ REX, const float* __restrict__ X,
                           const unsigned char* __restrict__ m, float* __restrict__ acc) {
    int warp = threadIdx.x >> 5, lane = threadIdx.x & 31;
    int row = blockIdx.x * 8 + warp;
    float contrib = 0.f;
    if (row < NNODES) {
        float4 a = ((const float4*)(REX + (size_t)row * D_IN))[lane];
        float4 b = ((const float4*)(X   + (size_t)row * D_IN))[lane];
        float dot = a.x * b.x + a.y * b.y + a.z * b.z + a.w * b.w;
        float na  = a.x * a.x + a.y * a.y + a.z * a.z + a.w * a.w;
        float nb  = b.x * b.x + b.y * b.y + b.z * b.z + b.w * b.w;
#pragma unroll
        for (int o = 16; o; o >>= 1) {
            dot += __shfl_down_sync(0xffffffffu, dot, o);
            na  += __shfl_down_sync(0xffffffffu, na , o);
            nb  += __shfl_down_sync(0xffffffffu, nb , o);
        }
        if (lane == 0 && m[row]) {
            float c = dot / (fmaxf(sqrtf(na), 1e-12f) * fmaxf(sqrtf(nb), 1e-12f));
            contrib = 1.f - c;
        }
    }
    __shared__ float s[8];
    if (lane == 0) s[warp] = contrib;
    __syncthreads();
    if (threadIdx.x == 0) {
        float t = 0.f;
#pragma unroll
        for (int j = 0; j < 8; ++j) t += s[j];
        atomicAdd(acc, t);
    }
}

__global__ void cl_k(const float* __restrict__ A, const float* __restrict__ B, float* __restrict__ acc) {
    int warp = threadIdx.x >> 5, lane = threadIdx.x & 31;
    int row = blockIdx.x * 8 + warp;
    float contrib = 0.f;
    if (row < NNODES) {
        float4 a = ((const float4*)(A + (size_t)row * D_IN))[lane];
        float4 b = ((const float4*)(B + (size_t)row * D_IN))[lane];
        float dot = a.x * b.x + a.y * b.y + a.z * b.z + a.w * b.w;
        float na  = a.x * a.x + a.y * a.y + a.z * a.z + a.w * a.w;
        float nb  = b.x * b.x + b.y * b.y + b.z * b.z + b.w * b.w;
#pragma unroll
        for (int o = 16; o; o >>= 1) {
            dot += __shfl_down_sync(0xffffffffu, dot, o);
            na  += __shfl_down_sync(0xffffffffu, na , o);
            nb  += __shfl_down_sync(0xffffffffu, nb , o);
        }
        if (lane == 0) {
            float c = dot / (fmaxf(sqrtf(na), 1e-12f) * fmaxf(sqrtf(nb), 1e-12f));
            contrib = 1.f - c;
        }
    }
    __shared__ float s[8];
    if (lane == 0) s[warp] = contrib;
    __syncthreads();
    if (threadIdx.x == 0) {
        float t = 0.f;
#pragma unroll
        for (int j = 0; j < 8; ++j) t += s[j];
        atomicAdd(acc, t);
    }
}

__global__ void final_k(float* __restrict__ out) {
    out[0] = g_acc[0] / g_acc[3] + g_acc[1] / g_acc[4] + 0.1f * (g_acc[2] / (float)NNODES);
}

extern "C" void kernel_launch(void* const* d_in, const int* in_sizes, int n_in,
                              void* d_out, int out_size) {
    const float* x = (const float*)d_in[0];
    const int* e1raw = (const int*)d_in[1];
    const int* e2raw = (const int*)d_in[2];
    const unsigned char* m1raw = (const unsigned char*)d_in[3];
    const unsigned char* m2raw = (const unsigned char*)d_in[4];
    // d_in[5] = batch : unused (pooled output discarded by reference)
    const float* e0_w1 = (const float*)d_in[6];
    const float* e0_w2 = (const float*)d_in[7];
    const float* e0_bg = (const float*)d_in[8];
    const float* e0_bb = (const float*)d_in[9];
    const float* e0_ng = (const float*)d_in[10];
    const float* e0_nb = (const float*)d_in[11];
    const float* e1_w1 = (const float*)d_in[12];
    const float* e1_w2 = (const float*)d_in[13];
    const float* e1_bg = (const float*)d_in[14];
    const float* e1_bb = (const float*)d_in[15];
    const float* e1_ng = (const float*)d_in[16];
    const float* e1_nb = (const float*)d_in[17];
    const float* dw1   = (const float*)d_in[18];
    const float* dw2   = (const float*)d_in[19];
    const float* dbg   = (const float*)d_in[20];
    const float* dbb   = (const float*)d_in[21];
    const float* dng   = (const float*)d_in[22];
    const float* dnb   = (const float*)d_in[23];
    float* out = (float*)d_out;

    float *p_agg, *p_T, *p_V, *p_REX1, *p_REX2;
    float *p_stats, *p_sc1, *p_sh1, *p_sc2, *p_sh2, *p_acc;
    int *p_src1, *p_dst1, *p_src2, *p_dst2;
    unsigned char *p_mA, *p_mB;
    __nv_bfloat16* p_wb;
    cudaGetSymbolAddress((void**)&p_agg,  g_agg);
    cudaGetSymbolAddress((void**)&p_T,    g_T);
    cudaGetSymbolAddress((void**)&p_V,    g_V);
    cudaGetSymbolAddress((void**)&p_REX1, g_REX1);
    cudaGetSymbolAddress((void**)&p_REX2, g_REX2);
    cudaGetSymbolAddress((void**)&p_stats,g_stats);
    cudaGetSymbolAddress((void**)&p_sc1,  g_sc1);
    cudaGetSymbolAddress((void**)&p_sh1,  g_sh1);
    cudaGetSymbolAddress((void**)&p_sc2,  g_sc2);
    cudaGetSymbolAddress((void**)&p_sh2,  g_sh2);
    cudaGetSymbolAddress((void**)&p_acc,  g_acc);
    cudaGetSymbolAddress((void**)&p_src1, g_src1);
    cudaGetSymbolAddress((void**)&p_dst1, g_dst1);
    cudaGetSymbolAddress((void**)&p_src2, g_src2);
    cudaGetSymbolAddress((void**)&p_dst2, g_dst2);
    cudaGetSymbolAddress((void**)&p_mA,   g_mA);
    cudaGetSymbolAddress((void**)&p_mB,   g_mB);
    cudaGetSymbolAddress((void**)&p_wb,   g_wb);

    float* p_sum = p_stats;
    float* p_sq  = p_stats + D_HID;

    // bf16 weight table offsets
    __nv_bfloat16* wb_e0w1 = p_wb + 0;
    __nv_bfloat16* wb_e0w2 = p_wb + 65536;
    __nv_bfloat16* wb_e1w1 = p_wb + 196608;
    __nv_bfloat16* wb_e1w2 = p_wb + 327680;
    __nv_bfloat16* wb_dw1  = p_wb + 458752;
    __nv_bfloat16* wb_dw2  = p_wb + 589824;

    cudaMemsetAsync(p_acc, 0, 8 * sizeof(float));

    detect_k<<<1, 32>>>(e1raw, m1raw);
    convedge_k<<<(NKEEP + 255) / 256, 256>>>(e1raw, p_src1, p_dst1);
    convedge_k<<<(NKEEP + 255) / 256, 256>>>(e2raw, p_src2, p_dst2);
    convmask_k<<<(NNODES + 255) / 256, 256>>>(m1raw, p_mA, p_acc + 3);
    convmask_k<<<(NNODES + 255) / 256, 256>>>(m2raw, p_mB, p_acc + 4);
    convw_k<<<(65536  + 255) / 256, 256>>>(e0_w1, wb_e0w1, 65536);
    convw_k<<<(131072 + 255) / 256, 256>>>(e0_w2, wb_e0w2, 131072);
    convw_k<<<(131072 + 255) / 256, 256>>>(e1_w1, wb_e1w1, 131072);
    convw_k<<<(131072 + 255) / 256, 256>>>(e1_w2, wb_e1w2, 131072);
    convw_k<<<(131072 + 255) / 256, 256>>>(dw1,   wb_dw1,  131072);
    convw_k<<<(65536  + 255) / 256, 256>>>(dw2,   wb_dw2,  65536);

    const int MB = (NNODES + 127) / 128;     // 391 row blocks
    dim3 s32(32, 8), s64(64, 4);             // scatter block shapes for d4=32 / 64
    const unsigned sg32 = (NKEEP + 7) / 8, sg64 = (NKEEP + 3) / 4;

    for (int pass = 0; pass < 2; ++pass) {
        const int* src = pass ? p_src2 : p_src1;
        const int* dst = pass ? p_dst2 : p_dst1;
        const unsigned char* m = pass ? p_mB : p_mA;
        float* REX = pass ? p_REX2 : p_REX1;

        // ---- encoder layer 0 : agg = masked x + scatter(masked x) ----
        maskagg_k<<<(unsigned)(((size_t)NNODES * D_IN + 255) / 256), 256>>>(x, p_agg, m);
        scatter_k<false, true><<<sg32, s32>>>(x, p_agg, src, dst, D_IN / 4, nullptr, nullptr, m);
        bgemm_k<false><<<dim3(D_HID / 128, MB), 256>>>(p_agg, wb_e0w1, p_T, NNODES, D_IN, D_HID, nullptr, nullptr, p_sum, p_sq);
        scaleshift_k<<<2, 256>>>(p_sum, p_sq, e0_bg, e0_bb, p_sc1, p_sh1, D_HID);
        bgemm_k<true><<<dim3(D_OUT / 128, MB), 256>>>(p_T, wb_e0w2, p_V, NNODES, D_HID, D_OUT, p_sc1, p_sh1, p_sum, p_sq);
        scaleshift_k<<<1, 256>>>(p_sum, p_sq, e0_ng, e0_nb, p_sc2, p_sh2, D_OUT);
        // agg(next) = relu(bn(V))  [unmasked]
        postbn_k<<<(unsigned)(((size_t)NNODES * D_OUT + 255) / 256), 256>>>(p_V, p_agg, p_sc2, p_sh2, nullptr, D_OUT, 8);

        // ---- encoder layer 1 : scatter gathers relu(bn(V0)) on the fly ----
        scatter_k<true, false><<<sg64, s64>>>(p_V, p_agg, src, dst, D_OUT / 4, p_sc2, p_sh2, nullptr);
        bgemm_k<false><<<dim3(D_HID / 128, MB), 256>>>(p_agg, wb_e1w1, p_T, NNODES, D_OUT, D_HID, nullptr, nullptr, p_sum, p_sq);
        scaleshift_k<<<2, 256>>>(p_sum, p_sq, e1_bg, e1_bb, p_sc1, p_sh1, D_HID);
        bgemm_k<true><<<dim3(D_OUT / 128, MB), 256>>>(p_T, wb_e1w2, p_V, NNODES, D_HID, D_OUT, p_sc1, p_sh1, p_sum, p_sq);
        scaleshift_k<<<1, 256>>>(p_sum, p_sq, e1_ng, e1_nb, p_sc2, p_sh2, D_OUT);
        // agg(decoder) = mask ? 0 : relu(bn(V1))   [re_h mask]
        postbn_k<<<(unsigned)(((size_t)NNODES * D_OUT + 255) / 256), 256>>>(p_V, p_agg, p_sc2, p_sh2, m, D_OUT, 8);

        // ---- decoder : scatter gathers masked relu(bn(V1)) on the fly ----
        scatter_k<true, true><<<sg64, s64>>>(p_V, p_agg, src, dst, D_OUT / 4, p_sc2, p_sh2, m);
        bgemm_k<false><<<dim3(D_HID / 128, MB), 256>>>(p_agg, wb_dw1, p_T, NNODES, D_OUT, D_HID, nullptr, nullptr, p_sum, p_sq);
        scaleshift_k<<<2, 256>>>(p_sum, p_sq, dbg, dbb, p_sc1, p_sh1, D_HID);
        bgemm_k<true><<<dim3(D_IN / 128, MB), 256>>>(p_T, wb_dw2, p_V, NNODES, D_HID, D_IN, p_sc1, p_sh1, p_sum, p_sq);
        scaleshift_k<<<1, 128>>>(p_sum, p_sq, dng, dnb, p_sc2, p_sh2, D_IN);
        postbn_k<<<(unsigned)(((size_t)NNODES * D_IN + 255) / 256), 256>>>(p_V, REX, p_sc2, p_sh2, nullptr, D_IN, 7);

        passloss_k<<<(NNODES + 7) / 8, 256>>>(REX, x, m, p_acc + pass);
    }

    cl_k<<<(NNODES + 7) / 8, 256>>>(p_REX2, p_REX1, p_acc + 2);
    final_k<<<1, 1>>>(out);
    (void)in_sizes; (void)n_in; (void)out_size;
}